// round 2
// baseline (speedup 1.0000x reference)
#include <cuda_runtime.h>
#include <cuda_fp16.h>
#include <stdint.h>
#include <math.h>

// ---------------- problem constants ----------------
#define N_TOK 32768      // B*T = 4*8192
#define C_DIM 1024
#define HS    2048
#define HR    1024
#define NE    8

// ---------------- GEMM tile config ----------------
#define BM 128
#define BN 128
#define BK 32
#define ASTR (BK + 8)    // 40 halfs/row  (80B, conflict-free for ldmatrix)
#define BSTR (BN + 8)    // 136 halfs/row (272B, conflict-free for ldmatrix.trans)

// ---------------- static scratch (no allocations allowed) ----------------
__device__ __half g_xh[N_TOK * C_DIM];          // x in fp16
__device__ __half g_sw1h[C_DIM * HS];
__device__ __half g_sw3h[C_DIM * HS];
__device__ __half g_sw2h[HS * C_DIM];
__device__ __half g_w1h[NE * C_DIM * HR];
__device__ __half g_w2h[NE * HR * C_DIM];
__device__ __half g_H1[N_TOK * HS];             // silu(x@sw1+b1)
__device__ __half g_H2[N_TOK * HS];             // H1 * (x@sw3+b3)
__device__ __half g_Hr[2 * N_TOK * HR];         // routed hidden, grouped [k][r][4096][HR]

// ---------------- small PTX helpers ----------------
__device__ __forceinline__ void cp16(void* s, const void* g) {
    unsigned sa = (unsigned)__cvta_generic_to_shared(s);
    asm volatile("cp.async.cg.shared.global [%0], [%1], 16;" :: "r"(sa), "l"(g));
}
__device__ __forceinline__ void ldsm4(uint32_t* r, const __half* p) {
    unsigned a = (unsigned)__cvta_generic_to_shared(p);
    asm volatile("ldmatrix.sync.aligned.m8n8.x4.shared.b16 {%0,%1,%2,%3}, [%4];"
                 : "=r"(r[0]), "=r"(r[1]), "=r"(r[2]), "=r"(r[3]) : "r"(a));
}
__device__ __forceinline__ void ldsm4t(uint32_t* r, const __half* p) {
    unsigned a = (unsigned)__cvta_generic_to_shared(p);
    asm volatile("ldmatrix.sync.aligned.m8n8.x4.trans.shared.b16 {%0,%1,%2,%3}, [%4];"
                 : "=r"(r[0]), "=r"(r[1]), "=r"(r[2]), "=r"(r[3]) : "r"(a));
}
__device__ __forceinline__ void mma16816(float* d, const uint32_t* a, const uint32_t* b) {
    asm volatile(
        "mma.sync.aligned.m16n8k16.row.col.f32.f16.f16.f32 "
        "{%0,%1,%2,%3},{%4,%5,%6,%7},{%8,%9},{%0,%1,%2,%3};"
        : "+f"(d[0]), "+f"(d[1]), "+f"(d[2]), "+f"(d[3])
        : "r"(a[0]), "r"(a[1]), "r"(a[2]), "r"(a[3]), "r"(b[0]), "r"(b[1]));
}

// ---------------- conversion kernel (fp32 -> fp16, vectorized x4) ----------------
__device__ __forceinline__ __half* conv_dst(int tag) {
    switch (tag) {
        case 0: return g_xh;
        case 1: return g_sw1h;
        case 2: return g_sw3h;
        case 3: return g_sw2h;
        case 4: return g_w1h;
        default: return g_w2h;
    }
}
__global__ void k_convert(const float* __restrict__ src, int tag, int n4) {
    int i = blockIdx.x * blockDim.x + threadIdx.x;
    if (i >= n4) return;
    float4 v = ((const float4*)src)[i];
    __half2* d = (__half2*)conv_dst(tag);
    d[2 * i]     = __floats2half2_rn(v.x, v.y);
    d[2 * i + 1] = __floats2half2_rn(v.z, v.w);
}

// ---------------- tile prefetch (cp.async) ----------------
__device__ __forceinline__ void prefetch_tile(
    const __half* __restrict__ A, int strideA,
    const __half* __restrict__ B, int ldb,
    int m0, int n0, int kt, __half* Asb, __half* Bsb, int tid)
{
#pragma unroll
    for (int i = 0; i < 2; i++) {              // A: 128x32 halfs = 512 x 16B chunks
        int c = tid + i * 256;
        int ar = c >> 2, ac = c & 3;
        cp16(Asb + ar * ASTR + ac * 8,
             A + (size_t)(m0 + ar) * strideA + kt * BK + ac * 8);
    }
#pragma unroll
    for (int i = 0; i < 2; i++) {              // B: 32x128 halfs = 512 x 16B chunks
        int c = tid + i * 256;
        int br = c >> 4, bc = c & 15;
        cp16(Bsb + br * BSTR + bc * 8,
             B + (size_t)(kt * BK + br) * ldb + n0 + bc * 8);
    }
}

// ---------------- fused GEMM core ----------------
// MODE 0: out(h) = silu(acc+bias)
// MODE 1: out(h) = aux * (acc+bias)
// MODE 2: out(f) = 0.5*(acc+bias)          (assign)
// MODE 3: out(h) = gelu_exact(acc+bias)
// MODE 4: out(f) += 0.25*(acc+bias)
template <int MODE>
__device__ __forceinline__ void gemm_core(
    const __half* __restrict__ A, int strideA,
    const __half* __restrict__ B, int ldb,
    const float* __restrict__ bias,
    const __half* __restrict__ aux, int strideAux,
    void* __restrict__ outp, int strideOut,
    int K)
{
    __shared__ __align__(16) __half As[2][BM * ASTR];
    __shared__ __align__(16) __half Bs[2][BK * BSTR];

    const int tid = threadIdx.x;
    const int m0 = blockIdx.y * BM;
    const int n0 = blockIdx.x * BN;
    const int KT = K / BK;

    prefetch_tile(A, strideA, B, ldb, m0, n0, 0, As[0], Bs[0], tid);
    asm volatile("cp.async.commit_group;");
    prefetch_tile(A, strideA, B, ldb, m0, n0, 1, As[1], Bs[1], tid);
    asm volatile("cp.async.commit_group;");

    float acc[2][8][4];
#pragma unroll
    for (int i = 0; i < 2; i++)
#pragma unroll
        for (int j = 0; j < 8; j++)
#pragma unroll
            for (int e = 0; e < 4; e++) acc[i][j][e] = 0.f;

    const int warp = tid >> 5, lane = tid & 31;
    const int wm = warp & 3, wn = warp >> 2;   // warp tile: 32 rows x 64 cols

    for (int kt = 0; kt < KT; ++kt) {
        const int st = kt & 1;
        asm volatile("cp.async.wait_group 1;");
        __syncthreads();

#pragma unroll
        for (int s = 0; s < 2; s++) {          // two k16 steps per BK=32
            uint32_t a[2][4], b[4][4];
#pragma unroll
            for (int mi = 0; mi < 2; mi++) {
                const __half* p = &As[st][(wm * 32 + mi * 16 + (lane & 15)) * ASTR
                                          + s * 16 + (lane >> 4) * 8];
                ldsm4(a[mi], p);
            }
#pragma unroll
            for (int p4 = 0; p4 < 4; p4++) {   // 16 cols per ldmatrix.x4.trans
                const __half* p = &Bs[st][(s * 16 + (lane & 7) + ((lane >> 3) & 1) * 8) * BSTR
                                          + wn * 64 + p4 * 16 + (lane >> 4) * 8];
                ldsm4t(b[p4], p);
            }
#pragma unroll
            for (int mi = 0; mi < 2; mi++)
#pragma unroll
                for (int ni = 0; ni < 8; ni++)
                    mma16816(acc[mi][ni], a[mi], &b[ni >> 1][(ni & 1) * 2]);
        }
        __syncthreads();
        if (kt + 2 < KT)
            prefetch_tile(A, strideA, B, ldb, m0, n0, kt + 2, As[st], Bs[st], tid);
        asm volatile("cp.async.commit_group;");
    }

    // ---- epilogue ----
#pragma unroll
    for (int mi = 0; mi < 2; mi++)
#pragma unroll
        for (int ni = 0; ni < 8; ni++)
#pragma unroll
            for (int pp = 0; pp < 2; pp++) {
                int row = m0 + wm * 32 + mi * 16 + (lane >> 2) + pp * 8;
                int col = n0 + wn * 64 + ni * 8 + (lane & 3) * 2;
                float v0 = acc[mi][ni][2 * pp + 0] + bias[col];
                float v1 = acc[mi][ni][2 * pp + 1] + bias[col + 1];
                if constexpr (MODE == 0) {
                    v0 = v0 / (1.f + __expf(-v0));
                    v1 = v1 / (1.f + __expf(-v1));
                    *(__half2*)((__half*)outp + (size_t)row * strideOut + col) =
                        __floats2half2_rn(v0, v1);
                } else if constexpr (MODE == 1) {
                    __half2 g = *(const __half2*)(aux + (size_t)row * strideAux + col);
                    v0 *= __low2float(g);
                    v1 *= __high2float(g);
                    *(__half2*)((__half*)outp + (size_t)row * strideOut + col) =
                        __floats2half2_rn(v0, v1);
                } else if constexpr (MODE == 2) {
                    float2 f; f.x = 0.5f * v0; f.y = 0.5f * v1;
                    *(float2*)((float*)outp + (size_t)row * strideOut + col) = f;
                } else if constexpr (MODE == 3) {
                    v0 = 0.5f * v0 * (1.f + erff(v0 * 0.70710678118654752f));
                    v1 = 0.5f * v1 * (1.f + erff(v1 * 0.70710678118654752f));
                    *(__half2*)((__half*)outp + (size_t)row * strideOut + col) =
                        __floats2half2_rn(v0, v1);
                } else {
                    float* o = (float*)outp + (size_t)row * strideOut + col;
                    float2 f = *(float2*)o;
                    f.x += 0.25f * v0; f.y += 0.25f * v1;
                    *(float2*)o = f;
                }
            }
}

// ---------------- kernel wrappers ----------------
__global__ __launch_bounds__(256, 1) void k_up1(const float* __restrict__ sb1) {
    gemm_core<0>(g_xh, C_DIM, g_sw1h, HS, sb1, nullptr, 0, g_H1, HS, C_DIM);
}
__global__ __launch_bounds__(256, 1) void k_up3(const float* __restrict__ sb3) {
    gemm_core<1>(g_xh, C_DIM, g_sw3h, HS, sb3, g_H1, HS, g_H2, HS, C_DIM);
}
__global__ __launch_bounds__(256, 1) void k_down_shared(const float* __restrict__ sb2,
                                                        float* __restrict__ dout) {
    gemm_core<2>(g_H2, HS, g_sw2h, C_DIM, sb2, nullptr, 0, dout, C_DIM, HS);
}
// residue class r (= token mod 8), hash slot k: expert e = (3r + 7k) mod 8.
// A rows are token t = r + 8*j  (j = logical row) -> strided access, no gather needed.
__global__ __launch_bounds__(256, 1) void k_routed_up(const float* __restrict__ b1) {
    int z = blockIdx.z;                 // z = kk*8 + rr
    int rr = z & 7, kk = z >> 3;
    int e = (3 * rr + 7 * kk) & 7;
    gemm_core<3>(g_xh + rr * C_DIM, 8 * C_DIM,
                 g_w1h + (size_t)e * C_DIM * HR, HR,
                 b1 + e * HR, nullptr, 0,
                 g_Hr + (size_t)z * 4096 * HR, HR, C_DIM);
}
__global__ __launch_bounds__(256, 1) void k_routed_down(const float* __restrict__ b2,
                                                        float* __restrict__ dout, int kk) {
    int rr = blockIdx.z;
    int e = (3 * rr + 7 * kk) & 7;
    int z = kk * 8 + rr;
    gemm_core<4>(g_Hr + (size_t)z * 4096 * HR, HR,
                 g_w2h + (size_t)e * HR * C_DIM, C_DIM,
                 b2 + e * C_DIM, nullptr, 0,
                 dout + rr * C_DIM, 8 * C_DIM, HR);
}

// ---------------- launch ----------------
extern "C" void kernel_launch(void* const* d_in, const int* in_sizes, int n_in,
                              void* d_out, int out_size) {
    const float* x   = (const float*)d_in[0];
    // d_in[1] = t_emb : unused by reference
    const float* sw1 = (const float*)d_in[2];
    const float* sb1 = (const float*)d_in[3];
    const float* sw3 = (const float*)d_in[4];
    const float* sb3 = (const float*)d_in[5];
    const float* sw2 = (const float*)d_in[6];
    const float* sb2 = (const float*)d_in[7];
    const float* w1  = (const float*)d_in[8];
    const float* b1  = (const float*)d_in[9];
    const float* w2  = (const float*)d_in[10];
    const float* b2  = (const float*)d_in[11];
    float* out = (float*)d_out;

    // fp32 -> fp16 conversions (deterministic each call)
    {
        struct { const float* p; int tag; int n; } cv[6] = {
            { x,   0, N_TOK * C_DIM },
            { sw1, 1, C_DIM * HS },
            { sw3, 2, C_DIM * HS },
            { sw2, 3, HS * C_DIM },
            { w1,  4, NE * C_DIM * HR },
            { w2,  5, NE * HR * C_DIM },
        };
        for (int i = 0; i < 6; i++) {
            int n4 = cv[i].n / 4;
            k_convert<<<(n4 + 255) / 256, 256>>>(cv[i].p, cv[i].tag, n4);
        }
    }

    // shared SwiGLU expert
    k_up1<<<dim3(HS / BN, N_TOK / BM), 256>>>(sb1);
    k_up3<<<dim3(HS / BN, N_TOK / BM), 256>>>(sb3);
    k_down_shared<<<dim3(C_DIM / BN, N_TOK / BM), 256>>>(sb2, out);

    // routed experts: 16 group-GEMMs up (parallel, disjoint outputs),
    // down split by k (both k's accumulate into the same token rows)
    k_routed_up<<<dim3(HR / BN, 4096 / BM, 16), 256>>>(b1);
    k_routed_down<<<dim3(C_DIM / BN, 4096 / BM, 8), 256>>>(b2, out, 0);
    k_routed_down<<<dim3(C_DIM / BN, 4096 / BM, 8), 256>>>(b2, out, 1);
}

// round 3
// speedup vs baseline: 1.0015x; 1.0015x over previous
#include <cuda_runtime.h>
#include <cuda_fp16.h>
#include <stdint.h>
#include <math.h>

// ---------------- problem constants ----------------
#define N_TOK 32768      // B*T = 4*8192
#define C_DIM 1024
#define HS    2048
#define HR    1024
#define NE    8

// ---------------- GEMM tile config ----------------
#define BM 128
#define BN 128
#define BK 32
#define ASTR (BK + 8)    // 40 halfs/row  (80B, conflict-free for ldmatrix)
#define BSTR (BN + 8)    // 136 halfs/row (272B, conflict-free for ldmatrix.trans)

// ---------------- static scratch (no allocations allowed) ----------------
__device__ __half g_xh[N_TOK * C_DIM];          // x in fp16
__device__ __half g_sw1h[C_DIM * HS];
__device__ __half g_sw3h[C_DIM * HS];
__device__ __half g_sw2h[HS * C_DIM];
__device__ __half g_w1h[NE * C_DIM * HR];
__device__ __half g_w2h[NE * HR * C_DIM];
__device__ __half g_H1[N_TOK * HS];             // silu(x@sw1+b1)
__device__ __half g_H2[N_TOK * HS];             // H1 * (x@sw3+b3)
__device__ __half g_Hr[2 * N_TOK * HR];         // routed hidden, grouped [k][r][4096][HR]

// ---------------- small PTX helpers ----------------
__device__ __forceinline__ void cp16(void* s, const void* g) {
    unsigned sa = (unsigned)__cvta_generic_to_shared(s);
    asm volatile("cp.async.cg.shared.global [%0], [%1], 16;" :: "r"(sa), "l"(g));
}
__device__ __forceinline__ void ldsm4(uint32_t* r, const __half* p) {
    unsigned a = (unsigned)__cvta_generic_to_shared(p);
    asm volatile("ldmatrix.sync.aligned.m8n8.x4.shared.b16 {%0,%1,%2,%3}, [%4];"
                 : "=r"(r[0]), "=r"(r[1]), "=r"(r[2]), "=r"(r[3]) : "r"(a));
}
__device__ __forceinline__ void ldsm4t(uint32_t* r, const __half* p) {
    unsigned a = (unsigned)__cvta_generic_to_shared(p);
    asm volatile("ldmatrix.sync.aligned.m8n8.x4.trans.shared.b16 {%0,%1,%2,%3}, [%4];"
                 : "=r"(r[0]), "=r"(r[1]), "=r"(r[2]), "=r"(r[3]) : "r"(a));
}
__device__ __forceinline__ void mma16816(float* d, const uint32_t* a, const uint32_t* b) {
    asm volatile(
        "mma.sync.aligned.m16n8k16.row.col.f32.f16.f16.f32 "
        "{%0,%1,%2,%3},{%4,%5,%6,%7},{%8,%9},{%0,%1,%2,%3};"
        : "+f"(d[0]), "+f"(d[1]), "+f"(d[2]), "+f"(d[3])
        : "r"(a[0]), "r"(a[1]), "r"(a[2]), "r"(a[3]), "r"(b[0]), "r"(b[1]));
}

// ---------------- conversion kernel (fp32 -> fp16, vectorized x4) ----------------
__device__ __forceinline__ __half* conv_dst(int tag) {
    switch (tag) {
        case 0: return g_xh;
        case 1: return g_sw1h;
        case 2: return g_sw3h;
        case 3: return g_sw2h;
        case 4: return g_w1h;
        default: return g_w2h;
    }
}
__global__ void k_convert(const float* __restrict__ src, int tag, int n4) {
    int i = blockIdx.x * blockDim.x + threadIdx.x;
    if (i >= n4) return;
    float4 v = ((const float4*)src)[i];
    __half2* d = (__half2*)conv_dst(tag);
    d[2 * i]     = __floats2half2_rn(v.x, v.y);
    d[2 * i + 1] = __floats2half2_rn(v.z, v.w);
}

// ---------------- tile prefetch (cp.async) ----------------
__device__ __forceinline__ void prefetch_tile(
    const __half* __restrict__ A, int strideA,
    const __half* __restrict__ B, int ldb,
    int m0, int n0, int kt, __half* Asb, __half* Bsb, int tid)
{
#pragma unroll
    for (int i = 0; i < 2; i++) {              // A: 128x32 halfs = 512 x 16B chunks
        int c = tid + i * 256;
        int ar = c >> 2, ac = c & 3;
        cp16(Asb + ar * ASTR + ac * 8,
             A + (size_t)(m0 + ar) * strideA + kt * BK + ac * 8);
    }
#pragma unroll
    for (int i = 0; i < 2; i++) {              // B: 32x128 halfs = 512 x 16B chunks
        int c = tid + i * 256;
        int br = c >> 4, bc = c & 15;
        cp16(Bsb + br * BSTR + bc * 8,
             B + (size_t)(kt * BK + br) * ldb + n0 + bc * 8);
    }
}

// ---------------- fused GEMM core ----------------
// MODE 0: out(h) = silu(acc+bias)
// MODE 1: out(h) = aux * (acc+bias)
// MODE 2: out(f) = 0.5*(acc+bias)          (assign)
// MODE 3: out(h) = gelu_exact(acc+bias)
// MODE 4: out(f) += 0.25*(acc+bias)
template <int MODE>
__device__ __forceinline__ void gemm_core(
    const __half* __restrict__ A, int strideA,
    const __half* __restrict__ B, int ldb,
    const float* __restrict__ bias,
    const __half* __restrict__ aux, int strideAux,
    void* __restrict__ outp, int strideOut,
    int K)
{
    __shared__ __align__(16) __half As[2][BM * ASTR];
    __shared__ __align__(16) __half Bs[2][BK * BSTR];

    const int tid = threadIdx.x;
    const int m0 = blockIdx.y * BM;
    const int n0 = blockIdx.x * BN;
    const int KT = K / BK;

    prefetch_tile(A, strideA, B, ldb, m0, n0, 0, As[0], Bs[0], tid);
    asm volatile("cp.async.commit_group;");
    prefetch_tile(A, strideA, B, ldb, m0, n0, 1, As[1], Bs[1], tid);
    asm volatile("cp.async.commit_group;");

    float acc[2][8][4];
#pragma unroll
    for (int i = 0; i < 2; i++)
#pragma unroll
        for (int j = 0; j < 8; j++)
#pragma unroll
            for (int e = 0; e < 4; e++) acc[i][j][e] = 0.f;

    const int warp = tid >> 5, lane = tid & 31;
    const int wm = warp & 3, wn = warp >> 2;   // warp tile: 32 rows x 64 cols

    for (int kt = 0; kt < KT; ++kt) {
        const int st = kt & 1;
        asm volatile("cp.async.wait_group 1;");
        __syncthreads();

#pragma unroll
        for (int s = 0; s < 2; s++) {          // two k16 steps per BK=32
            uint32_t a[2][4], b[4][4];
#pragma unroll
            for (int mi = 0; mi < 2; mi++) {
                const __half* p = &As[st][(wm * 32 + mi * 16 + (lane & 15)) * ASTR
                                          + s * 16 + (lane >> 4) * 8];
                ldsm4(a[mi], p);
            }
#pragma unroll
            for (int p4 = 0; p4 < 4; p4++) {   // 16 cols per ldmatrix.x4.trans
                const __half* p = &Bs[st][(s * 16 + (lane & 7) + ((lane >> 3) & 1) * 8) * BSTR
                                          + wn * 64 + p4 * 16 + (lane >> 4) * 8];
                ldsm4t(b[p4], p);
            }
#pragma unroll
            for (int mi = 0; mi < 2; mi++)
#pragma unroll
                for (int ni = 0; ni < 8; ni++)
                    mma16816(acc[mi][ni], a[mi], &b[ni >> 1][(ni & 1) * 2]);
        }
        __syncthreads();
        if (kt + 2 < KT)
            prefetch_tile(A, strideA, B, ldb, m0, n0, kt + 2, As[st], Bs[st], tid);
        asm volatile("cp.async.commit_group;");
    }

    // ---- epilogue ----
#pragma unroll
    for (int mi = 0; mi < 2; mi++)
#pragma unroll
        for (int ni = 0; ni < 8; ni++)
#pragma unroll
            for (int pp = 0; pp < 2; pp++) {
                int row = m0 + wm * 32 + mi * 16 + (lane >> 2) + pp * 8;
                int col = n0 + wn * 64 + ni * 8 + (lane & 3) * 2;
                float v0 = acc[mi][ni][2 * pp + 0] + bias[col];
                float v1 = acc[mi][ni][2 * pp + 1] + bias[col + 1];
                if constexpr (MODE == 0) {
                    v0 = v0 / (1.f + __expf(-v0));
                    v1 = v1 / (1.f + __expf(-v1));
                    *(__half2*)((__half*)outp + (size_t)row * strideOut + col) =
                        __floats2half2_rn(v0, v1);
                } else if constexpr (MODE == 1) {
                    __half2 g = *(const __half2*)(aux + (size_t)row * strideAux + col);
                    v0 *= __low2float(g);
                    v1 *= __high2float(g);
                    *(__half2*)((__half*)outp + (size_t)row * strideOut + col) =
                        __floats2half2_rn(v0, v1);
                } else if constexpr (MODE == 2) {
                    float2 f; f.x = 0.5f * v0; f.y = 0.5f * v1;
                    *(float2*)((float*)outp + (size_t)row * strideOut + col) = f;
                } else if constexpr (MODE == 3) {
                    v0 = 0.5f * v0 * (1.f + erff(v0 * 0.70710678118654752f));
                    v1 = 0.5f * v1 * (1.f + erff(v1 * 0.70710678118654752f));
                    *(__half2*)((__half*)outp + (size_t)row * strideOut + col) =
                        __floats2half2_rn(v0, v1);
                } else {
                    float* o = (float*)outp + (size_t)row * strideOut + col;
                    float2 f = *(float2*)o;
                    f.x += 0.25f * v0; f.y += 0.25f * v1;
                    *(float2*)o = f;
                }
            }
}

// ---------------- kernel wrappers ----------------
__global__ __launch_bounds__(256, 1) void k_up1(const float* __restrict__ sb1) {
    gemm_core<0>(g_xh, C_DIM, g_sw1h, HS, sb1, nullptr, 0, g_H1, HS, C_DIM);
}
__global__ __launch_bounds__(256, 1) void k_up3(const float* __restrict__ sb3) {
    gemm_core<1>(g_xh, C_DIM, g_sw3h, HS, sb3, g_H1, HS, g_H2, HS, C_DIM);
}
__global__ __launch_bounds__(256, 1) void k_down_shared(const float* __restrict__ sb2,
                                                        float* __restrict__ dout) {
    gemm_core<2>(g_H2, HS, g_sw2h, C_DIM, sb2, nullptr, 0, dout, C_DIM, HS);
}
// residue class r (= token mod 8), hash slot k: expert e = (3r + 7k) mod 8.
// A rows are token t = r + 8*j  (j = logical row) -> strided access, no gather needed.
__global__ __launch_bounds__(256, 1) void k_routed_up(const float* __restrict__ b1) {
    int z = blockIdx.z;                 // z = kk*8 + rr
    int rr = z & 7, kk = z >> 3;
    int e = (3 * rr + 7 * kk) & 7;
    gemm_core<3>(g_xh + rr * C_DIM, 8 * C_DIM,
                 g_w1h + (size_t)e * C_DIM * HR, HR,
                 b1 + e * HR, nullptr, 0,
                 g_Hr + (size_t)z * 4096 * HR, HR, C_DIM);
}
__global__ __launch_bounds__(256, 1) void k_routed_down(const float* __restrict__ b2,
                                                        float* __restrict__ dout, int kk) {
    int rr = blockIdx.z;
    int e = (3 * rr + 7 * kk) & 7;
    int z = kk * 8 + rr;
    gemm_core<4>(g_Hr + (size_t)z * 4096 * HR, HR,
                 g_w2h + (size_t)e * HR * C_DIM, C_DIM,
                 b2 + e * C_DIM, nullptr, 0,
                 dout + rr * C_DIM, 8 * C_DIM, HR);
}

// ---------------- launch ----------------
extern "C" void kernel_launch(void* const* d_in, const int* in_sizes, int n_in,
                              void* d_out, int out_size) {
    const float* x   = (const float*)d_in[0];
    // d_in[1] = t_emb : unused by reference
    const float* sw1 = (const float*)d_in[2];
    const float* sb1 = (const float*)d_in[3];
    const float* sw3 = (const float*)d_in[4];
    const float* sb3 = (const float*)d_in[5];
    const float* sw2 = (const float*)d_in[6];
    const float* sb2 = (const float*)d_in[7];
    const float* w1  = (const float*)d_in[8];
    const float* b1  = (const float*)d_in[9];
    const float* w2  = (const float*)d_in[10];
    const float* b2  = (const float*)d_in[11];
    float* out = (float*)d_out;

    // fp32 -> fp16 conversions (deterministic each call)
    {
        struct { const float* p; int tag; int n; } cv[6] = {
            { x,   0, N_TOK * C_DIM },
            { sw1, 1, C_DIM * HS },
            { sw3, 2, C_DIM * HS },
            { sw2, 3, HS * C_DIM },
            { w1,  4, NE * C_DIM * HR },
            { w2,  5, NE * HR * C_DIM },
        };
        for (int i = 0; i < 6; i++) {
            int n4 = cv[i].n / 4;
            k_convert<<<(n4 + 255) / 256, 256>>>(cv[i].p, cv[i].tag, n4);
        }
    }

    // shared SwiGLU expert
    k_up1<<<dim3(HS / BN, N_TOK / BM), 256>>>(sb1);
    k_up3<<<dim3(HS / BN, N_TOK / BM), 256>>>(sb3);
    k_down_shared<<<dim3(C_DIM / BN, N_TOK / BM), 256>>>(sb2, out);

    // routed experts: 16 group-GEMMs up (parallel, disjoint outputs),
    // down split by k (both k's accumulate into the same token rows)
    k_routed_up<<<dim3(HR / BN, 4096 / BM, 16), 256>>>(b1);
    k_routed_down<<<dim3(C_DIM / BN, 4096 / BM, 8), 256>>>(b2, out, 0);
    k_routed_down<<<dim3(C_DIM / BN, 4096 / BM, 8), 256>>>(b2, out, 1);
}

// round 7
// speedup vs baseline: 1.6038x; 1.6014x over previous
#include <cuda_runtime.h>
#include <cuda_fp16.h>
#include <stdint.h>
#include <math.h>

// ---------------- problem constants ----------------
#define N_TOK 32768      // B*T = 4*8192
#define C_DIM 1024
#define HS    2048
#define HR    1024
#define NE    8

// ---------------- GEMM tile config ----------------
#define BM 128
#define BN 128
#define BK 32
#define NSTG 5
#define ASTR (BK + 8)    // 40 halfs/row  (80B, conflict-free for ldmatrix)
#define BSTR (BN + 8)    // 136 halfs/row (272B, conflict-free for ldmatrix.trans)
#define A_ST (BM * ASTR)             // halfs per A stage (10240B)
#define B_ST (BK * BSTR)             // halfs per B stage (8704B)
#define SMEM_BYTES (NSTG * (A_ST + B_ST) * 2)   // 94720 B

// ---------------- static scratch (no allocations allowed) ----------------
__device__ __half g_xh[N_TOK * C_DIM];          // x in fp16
__device__ __half g_sw1h[C_DIM * HS];
__device__ __half g_sw3h[C_DIM * HS];
__device__ __half g_sw2h[HS * C_DIM];
__device__ __half g_w1h[NE * C_DIM * HR];
__device__ __half g_w2h[NE * HR * C_DIM];
__device__ __half g_H1[N_TOK * HS];             // silu(x@sw1+b1)
__device__ __half g_H2[N_TOK * HS];             // H1 * (x@sw3+b3)
__device__ __half g_Hr[2 * N_TOK * HR];         // routed hidden, grouped [k][r][4096][HR]

// ---------------- small PTX helpers ----------------
__device__ __forceinline__ void cp16(void* s, const void* g) {
    unsigned sa = (unsigned)__cvta_generic_to_shared(s);
    asm volatile("cp.async.cg.shared.global [%0], [%1], 16;" :: "r"(sa), "l"(g));
}
__device__ __forceinline__ void ldsm4(uint32_t* r, const __half* p) {
    unsigned a = (unsigned)__cvta_generic_to_shared(p);
    asm volatile("ldmatrix.sync.aligned.m8n8.x4.shared.b16 {%0,%1,%2,%3}, [%4];"
                 : "=r"(r[0]), "=r"(r[1]), "=r"(r[2]), "=r"(r[3]) : "r"(a));
}
__device__ __forceinline__ void ldsm4t(uint32_t* r, const __half* p) {
    unsigned a = (unsigned)__cvta_generic_to_shared(p);
    asm volatile("ldmatrix.sync.aligned.m8n8.x4.trans.shared.b16 {%0,%1,%2,%3}, [%4];"
                 : "=r"(r[0]), "=r"(r[1]), "=r"(r[2]), "=r"(r[3]) : "r"(a));
}
__device__ __forceinline__ void mma16816(float* d, const uint32_t* a, const uint32_t* b) {
    asm volatile(
        "mma.sync.aligned.m16n8k16.row.col.f32.f16.f16.f32 "
        "{%0,%1,%2,%3},{%4,%5,%6,%7},{%8,%9},{%0,%1,%2,%3};"
        : "+f"(d[0]), "+f"(d[1]), "+f"(d[2]), "+f"(d[3])
        : "r"(a[0]), "r"(a[1]), "r"(a[2]), "r"(a[3]), "r"(b[0]), "r"(b[1]));
}

// ---------------- conversion kernel (fp32 -> fp16, vectorized x4) ----------------
__device__ __forceinline__ __half* conv_dst(int tag) {
    switch (tag) {
        case 0: return g_xh;
        case 1: return g_sw1h;
        case 2: return g_sw3h;
        case 3: return g_sw2h;
        case 4: return g_w1h;
        default: return g_w2h;
    }
}
__global__ void k_convert(const float* __restrict__ src, int tag, int n4) {
    int i = blockIdx.x * blockDim.x + threadIdx.x;
    if (i >= n4) return;
    float4 v = ((const float4*)src)[i];
    __half2* d = (__half2*)conv_dst(tag);
    d[2 * i]     = __floats2half2_rn(v.x, v.y);
    d[2 * i + 1] = __floats2half2_rn(v.z, v.w);
}

// ---------------- tile prefetch (cp.async) ----------------
__device__ __forceinline__ void fill_stage(
    const __half* __restrict__ A, int strideA,
    const __half* __restrict__ B, int ldb,
    int m0, int n0, int kt, __half* Asb, __half* Bsb, int tid)
{
#pragma unroll
    for (int i = 0; i < 2; i++) {              // A: 128x32 halfs = 512 x 16B chunks
        int c = tid + i * 256;
        int ar = c >> 2, ac = c & 3;
        cp16(Asb + ar * ASTR + ac * 8,
             A + (size_t)(m0 + ar) * strideA + kt * BK + ac * 8);
    }
#pragma unroll
    for (int i = 0; i < 2; i++) {              // B: 32x128 halfs = 512 x 16B chunks
        int c = tid + i * 256;
        int br = c >> 4, bc = c & 15;
        cp16(Bsb + br * BSTR + bc * 8,
             B + (size_t)(kt * BK + br) * ldb + n0 + bc * 8);
    }
}

// ---------------- fused GEMM core (5-stage cp.async, 1 sync/iter) ----------------
// MODE 0: out(h) = silu(acc+bias)
// MODE 1: out(h) = aux * (acc+bias)
// MODE 2: out(f) = 0.5*(acc+bias)          (assign)
// MODE 3: out(h) = gelu_exact(acc+bias)
// MODE 4: out(f) += 0.25*(acc+bias)
template <int MODE>
__device__ __forceinline__ void gemm_core(
    const __half* __restrict__ A, int strideA,
    const __half* __restrict__ B, int ldb,
    const float* __restrict__ bias,
    const __half* __restrict__ aux, int strideAux,
    void* __restrict__ outp, int strideOut,
    int K)
{
    extern __shared__ __align__(16) __half smem[];
    __half* Asm = smem;                       // NSTG stages of A
    __half* Bsm = smem + NSTG * A_ST;         // NSTG stages of B

    const int tid = threadIdx.x;
    const int m0 = blockIdx.y * BM;
    const int n0 = blockIdx.x * BN;
    const int KT = K / BK;

    // prologue: fill NSTG-1 stages
#pragma unroll
    for (int c = 0; c < NSTG - 1; c++) {
        fill_stage(A, strideA, B, ldb, m0, n0, c,
                   Asm + c * A_ST, Bsm + c * B_ST, tid);
        asm volatile("cp.async.commit_group;");
    }

    float acc[2][8][4];
#pragma unroll
    for (int i = 0; i < 2; i++)
#pragma unroll
        for (int j = 0; j < 8; j++)
#pragma unroll
            for (int e = 0; e < 4; e++) acc[i][j][e] = 0.f;

    const int warp = tid >> 5, lane = tid & 31;
    const int wm = warp & 3, wn = warp >> 2;   // warp tile: 32 rows x 64 cols

    int s = 0;                                 // compute stage
    int fs = NSTG - 1;                         // fill stage
    for (int kt = 0; kt < KT; ++kt) {
        asm volatile("cp.async.wait_group %0;" :: "n"(NSTG - 2));
        __syncthreads();

        const __half* As = Asm + s * A_ST;
        const __half* Bs = Bsm + s * B_ST;
#pragma unroll
        for (int ks = 0; ks < 2; ks++) {       // two k16 steps per BK=32
            uint32_t a[2][4];
#pragma unroll
            for (int mi = 0; mi < 2; mi++) {
                const __half* p = &As[(wm * 32 + mi * 16 + (lane & 15)) * ASTR
                                      + ks * 16 + (lane >> 4) * 8];
                ldsm4(a[mi], p);
            }
#pragma unroll
            for (int p4 = 0; p4 < 4; p4++) {   // 16 cols per ldmatrix.x4.trans
                uint32_t b[4];
                const __half* p = &Bs[(ks * 16 + (lane & 7) + ((lane >> 3) & 1) * 8) * BSTR
                                      + wn * 64 + p4 * 16 + (lane >> 4) * 8];
                ldsm4t(b, p);
                mma16816(acc[0][2 * p4 + 0], a[0], &b[0]);
                mma16816(acc[0][2 * p4 + 1], a[0], &b[2]);
                mma16816(acc[1][2 * p4 + 0], a[1], &b[0]);
                mma16816(acc[1][2 * p4 + 1], a[1], &b[2]);
            }
        }

        // refill the slot released at this iteration's sync: (kt+NSTG-1)%NSTG == (kt-1)%NSTG
        if (kt + NSTG - 1 < KT)
            fill_stage(A, strideA, B, ldb, m0, n0, kt + NSTG - 1,
                       Asm + fs * A_ST, Bsm + fs * B_ST, tid);
        asm volatile("cp.async.commit_group;");

        if (++s == NSTG) s = 0;
        if (++fs == NSTG) fs = 0;
    }

    // ---- epilogue ----
#pragma unroll
    for (int mi = 0; mi < 2; mi++)
#pragma unroll
        for (int ni = 0; ni < 8; ni++)
#pragma unroll
            for (int pp = 0; pp < 2; pp++) {
                int row = m0 + wm * 32 + mi * 16 + (lane >> 2) + pp * 8;
                int col = n0 + wn * 64 + ni * 8 + (lane & 3) * 2;
                float v0 = acc[mi][ni][2 * pp + 0] + bias[col];
                float v1 = acc[mi][ni][2 * pp + 1] + bias[col + 1];
                if constexpr (MODE == 0) {
                    v0 = v0 / (1.f + __expf(-v0));
                    v1 = v1 / (1.f + __expf(-v1));
                    *(__half2*)((__half*)outp + (size_t)row * strideOut + col) =
                        __floats2half2_rn(v0, v1);
                } else if constexpr (MODE == 1) {
                    __half2 g = *(const __half2*)(aux + (size_t)row * strideAux + col);
                    v0 *= __low2float(g);
                    v1 *= __high2float(g);
                    *(__half2*)((__half*)outp + (size_t)row * strideOut + col) =
                        __floats2half2_rn(v0, v1);
                } else if constexpr (MODE == 2) {
                    float2 f; f.x = 0.5f * v0; f.y = 0.5f * v1;
                    *(float2*)((float*)outp + (size_t)row * strideOut + col) = f;
                } else if constexpr (MODE == 3) {
                    v0 = 0.5f * v0 * (1.f + erff(v0 * 0.70710678118654752f));
                    v1 = 0.5f * v1 * (1.f + erff(v1 * 0.70710678118654752f));
                    *(__half2*)((__half*)outp + (size_t)row * strideOut + col) =
                        __floats2half2_rn(v0, v1);
                } else {
                    float* o = (float*)outp + (size_t)row * strideOut + col;
                    float2 f = *(float2*)o;
                    f.x += 0.25f * v0; f.y += 0.25f * v1;
                    *(float2*)o = f;
                }
            }
}

// ---------------- kernel wrappers ----------------
__global__ __launch_bounds__(256, 2) void k_up1(const float* __restrict__ sb1) {
    gemm_core<0>(g_xh, C_DIM, g_sw1h, HS, sb1, nullptr, 0, g_H1, HS, C_DIM);
}
__global__ __launch_bounds__(256, 2) void k_up3(const float* __restrict__ sb3) {
    gemm_core<1>(g_xh, C_DIM, g_sw3h, HS, sb3, g_H1, HS, g_H2, HS, C_DIM);
}
__global__ __launch_bounds__(256, 2) void k_down_shared(const float* __restrict__ sb2,
                                                        float* __restrict__ dout) {
    gemm_core<2>(g_H2, HS, g_sw2h, C_DIM, sb2, nullptr, 0, dout, C_DIM, HS);
}
// residue class r (= token mod 8), hash slot k: expert e = (3r + 7k) mod 8.
// A rows are token t = r + 8*j  (j = logical row) -> strided access, no gather needed.
__global__ __launch_bounds__(256, 2) void k_routed_up(const float* __restrict__ b1) {
    int z = blockIdx.z;                 // z = kk*8 + rr
    int rr = z & 7, kk = z >> 3;
    int e = (3 * rr + 7 * kk) & 7;
    gemm_core<3>(g_xh + rr * C_DIM, 8 * C_DIM,
                 g_w1h + (size_t)e * C_DIM * HR, HR,
                 b1 + e * HR, nullptr, 0,
                 g_Hr + (size_t)z * 4096 * HR, HR, C_DIM);
}
__global__ __launch_bounds__(256, 2) void k_routed_down(const float* __restrict__ b2,
                                                        float* __restrict__ dout, int kk) {
    int rr = blockIdx.z;
    int e = (3 * rr + 7 * kk) & 7;
    int z = kk * 8 + rr;
    gemm_core<4>(g_Hr + (size_t)z * 4096 * HR, HR,
                 g_w2h + (size_t)e * HR * C_DIM, C_DIM,
                 b2 + e * C_DIM, nullptr, 0,
                 dout + rr * C_DIM, 8 * C_DIM, HR);
}

// ---------------- launch ----------------
extern "C" void kernel_launch(void* const* d_in, const int* in_sizes, int n_in,
                              void* d_out, int out_size) {
    const float* x   = (const float*)d_in[0];
    // d_in[1] = t_emb : unused by reference
    const float* sw1 = (const float*)d_in[2];
    const float* sb1 = (const float*)d_in[3];
    const float* sw3 = (const float*)d_in[4];
    const float* sb3 = (const float*)d_in[5];
    const float* sw2 = (const float*)d_in[6];
    const float* sb2 = (const float*)d_in[7];
    const float* w1  = (const float*)d_in[8];
    const float* b1  = (const float*)d_in[9];
    const float* w2  = (const float*)d_in[10];
    const float* b2  = (const float*)d_in[11];
    float* out = (float*)d_out;

    static bool attr_done = false;
    // setting an attribute is idempotent & allocation-free; do it every call
    cudaFuncSetAttribute(k_up1,         cudaFuncAttributeMaxDynamicSharedMemorySize, SMEM_BYTES);
    cudaFuncSetAttribute(k_up3,         cudaFuncAttributeMaxDynamicSharedMemorySize, SMEM_BYTES);
    cudaFuncSetAttribute(k_down_shared, cudaFuncAttributeMaxDynamicSharedMemorySize, SMEM_BYTES);
    cudaFuncSetAttribute(k_routed_up,   cudaFuncAttributeMaxDynamicSharedMemorySize, SMEM_BYTES);
    cudaFuncSetAttribute(k_routed_down, cudaFuncAttributeMaxDynamicSharedMemorySize, SMEM_BYTES);
    (void)attr_done;

    // fp32 -> fp16 conversions (deterministic each call)
    {
        struct { const float* p; int tag; int n; } cv[6] = {
            { x,   0, N_TOK * C_DIM },
            { sw1, 1, C_DIM * HS },
            { sw3, 2, C_DIM * HS },
            { sw2, 3, HS * C_DIM },
            { w1,  4, NE * C_DIM * HR },
            { w2,  5, NE * HR * C_DIM },
        };
        for (int i = 0; i < 6; i++) {
            int n4 = cv[i].n / 4;
            k_convert<<<(n4 + 255) / 256, 256>>>(cv[i].p, cv[i].tag, n4);
        }
    }

    // shared SwiGLU expert
    k_up1<<<dim3(HS / BN, N_TOK / BM), 256, SMEM_BYTES>>>(sb1);
    k_up3<<<dim3(HS / BN, N_TOK / BM), 256, SMEM_BYTES>>>(sb3);
    k_down_shared<<<dim3(C_DIM / BN, N_TOK / BM), 256, SMEM_BYTES>>>(sb2, out);

    // routed experts: 16 group-GEMMs up (parallel, disjoint outputs),
    // down split by k (both k's accumulate into the same token rows)
    k_routed_up<<<dim3(HR / BN, 4096 / BM, 16), 256, SMEM_BYTES>>>(b1);
    k_routed_down<<<dim3(C_DIM / BN, 4096 / BM, 8), 256, SMEM_BYTES>>>(b2, out, 0);
    k_routed_down<<<dim3(C_DIM / BN, 4096 / BM, 8), 256, SMEM_BYTES>>>(b2, out, 1);
}

// round 8
// speedup vs baseline: 1.6978x; 1.0585x over previous
#include <cuda_runtime.h>
#include <cuda_fp16.h>
#include <stdint.h>
#include <math.h>

// ---------------- problem constants ----------------
#define N_TOK 32768      // B*T = 4*8192
#define C_DIM 1024
#define HS    2048
#define HR    1024
#define NE    8

// ---------------- GEMM tile config ----------------
#define BM 128
#define BN 128
#define BK 32
#define NSTG 5
#define ASTR (BK + 8)    // 40 halfs/row  (80B, conflict-free for ldmatrix)
#define BSTR (BN + 8)    // 136 halfs/row (272B, conflict-free for ldmatrix.trans)
#define A_ST (BM * ASTR)             // halfs per A stage (10240B)
#define B_ST (BK * BSTR)             // halfs per B stage (8704B)
#define SMEM_BYTES (NSTG * (A_ST + B_ST) * 2)   // 94720 B

// ---------------- static scratch (no allocations allowed) ----------------
__device__ __half g_xh[N_TOK * C_DIM];          // x in fp16
__device__ __half g_sw1h[C_DIM * HS];
__device__ __half g_sw3h[C_DIM * HS];
__device__ __half g_sw2h[HS * C_DIM];           // pre-scaled by 0.5
__device__ __half g_w1h[NE * C_DIM * HR];
__device__ __half g_w2h[NE * HR * C_DIM];       // pre-scaled by 0.25
__device__ __half g_H1[N_TOK * HS];             // silu(x@sw1+b1)
__device__ __half g_H2[N_TOK * HS];             // H1 * (x@sw3+b3)
__device__ __half g_Hr[2 * N_TOK * HR];         // routed hidden, grouped [k][r][4096][HR]

// ---------------- small PTX helpers ----------------
__device__ __forceinline__ void cp16(void* s, const void* g) {
    unsigned sa = (unsigned)__cvta_generic_to_shared(s);
    asm volatile("cp.async.cg.shared.global [%0], [%1], 16;" :: "r"(sa), "l"(g));
}
__device__ __forceinline__ void ldsm4(uint32_t* r, const __half* p) {
    unsigned a = (unsigned)__cvta_generic_to_shared(p);
    asm volatile("ldmatrix.sync.aligned.m8n8.x4.shared.b16 {%0,%1,%2,%3}, [%4];"
                 : "=r"(r[0]), "=r"(r[1]), "=r"(r[2]), "=r"(r[3]) : "r"(a));
}
__device__ __forceinline__ void ldsm4t(uint32_t* r, const __half* p) {
    unsigned a = (unsigned)__cvta_generic_to_shared(p);
    asm volatile("ldmatrix.sync.aligned.m8n8.x4.trans.shared.b16 {%0,%1,%2,%3}, [%4];"
                 : "=r"(r[0]), "=r"(r[1]), "=r"(r[2]), "=r"(r[3]) : "r"(a));
}
__device__ __forceinline__ void mma16816(float* d, const uint32_t* a, const uint32_t* b) {
    asm volatile(
        "mma.sync.aligned.m16n8k16.row.col.f32.f16.f16.f32 "
        "{%0,%1,%2,%3},{%4,%5,%6,%7},{%8,%9},{%0,%1,%2,%3};"
        : "+f"(d[0]), "+f"(d[1]), "+f"(d[2]), "+f"(d[3])
        : "r"(a[0]), "r"(a[1]), "r"(a[2]), "r"(a[3]), "r"(b[0]), "r"(b[1]));
}

// ---------------- conversion kernel (fp32 -> fp16, vectorized x4, scaled) ----------------
__device__ __forceinline__ __half* conv_dst(int tag) {
    switch (tag) {
        case 0: return g_xh;
        case 1: return g_sw1h;
        case 2: return g_sw3h;
        case 3: return g_sw2h;
        case 4: return g_w1h;
        default: return g_w2h;
    }
}
__global__ void k_convert(const float* __restrict__ src, int tag, int n4, float scale) {
    int i = blockIdx.x * blockDim.x + threadIdx.x;
    if (i >= n4) return;
    float4 v = ((const float4*)src)[i];
    __half2* d = (__half2*)conv_dst(tag);
    d[2 * i]     = __floats2half2_rn(v.x * scale, v.y * scale);
    d[2 * i + 1] = __floats2half2_rn(v.z * scale, v.w * scale);
}

// ---------------- stage fill (cp.async) ----------------
__device__ __forceinline__ void fill_stage(
    const __half* __restrict__ A, int strideA,
    const __half* __restrict__ B, int ldb,
    int m0, int n0, int kt, __half* Asb, __half* Bsb, int tid)
{
#pragma unroll
    for (int i = 0; i < 2; i++) {              // A: 128x32 halfs = 512 x 16B chunks
        int c = tid + i * 256;
        int ar = c >> 2, ac = c & 3;
        cp16(Asb + ar * ASTR + ac * 8,
             A + (size_t)(m0 + ar) * strideA + kt * BK + ac * 8);
    }
#pragma unroll
    for (int i = 0; i < 2; i++) {              // B: 32x128 halfs = 512 x 16B chunks
        int c = tid + i * 256;
        int br = c >> 4, bc = c & 15;
        cp16(Bsb + br * BSTR + bc * 8,
             B + (size_t)(kt * BK + br) * ldb + n0 + bc * 8);
    }
}

// ---------------- warp-tile compute on one resident stage ----------------
__device__ __forceinline__ void compute_stage(
    const __half* As, const __half* Bs, float acc[2][8][4],
    int wm, int wn, int lane)
{
#pragma unroll
    for (int ks = 0; ks < 2; ks++) {           // two k16 steps per BK=32
        uint32_t a[2][4];
#pragma unroll
        for (int mi = 0; mi < 2; mi++) {
            const __half* p = &As[(wm * 32 + mi * 16 + (lane & 15)) * ASTR
                                  + ks * 16 + (lane >> 4) * 8];
            ldsm4(a[mi], p);
        }
#pragma unroll
        for (int p4 = 0; p4 < 4; p4++) {       // 16 cols per ldmatrix.x4.trans
            uint32_t b[4];
            const __half* p = &Bs[(ks * 16 + (lane & 7) + ((lane >> 3) & 1) * 8) * BSTR
                                  + wn * 64 + p4 * 16 + (lane >> 4) * 8];
            ldsm4t(b, p);
            mma16816(acc[0][2 * p4 + 0], a[0], &b[0]);
            mma16816(acc[0][2 * p4 + 1], a[0], &b[2]);
            mma16816(acc[1][2 * p4 + 0], a[1], &b[0]);
            mma16816(acc[1][2 * p4 + 1], a[1], &b[2]);
        }
    }
}

// ---------------- fused GEMM core (5-stage cp.async, 1 sync/iter) ----------------
// MODE 0: out(h) = silu(acc+bias)
// MODE 1: out(h) = aux * (acc+bias)
// MODE 3: out(h) = gelu_exact(acc+bias)
template <int MODE>
__device__ __forceinline__ void gemm_core(
    const __half* __restrict__ A, int strideA,
    const __half* __restrict__ B, int ldb,
    const float* __restrict__ bias,
    const __half* __restrict__ aux, int strideAux,
    void* __restrict__ outp, int strideOut,
    int K)
{
    extern __shared__ __align__(16) __half smem[];
    __half* Asm = smem;
    __half* Bsm = smem + NSTG * A_ST;

    const int tid = threadIdx.x;
    const int m0 = blockIdx.y * BM;
    const int n0 = blockIdx.x * BN;
    const int KT = K / BK;

#pragma unroll
    for (int c = 0; c < NSTG - 1; c++) {
        fill_stage(A, strideA, B, ldb, m0, n0, c,
                   Asm + c * A_ST, Bsm + c * B_ST, tid);
        asm volatile("cp.async.commit_group;");
    }

    float acc[2][8][4];
#pragma unroll
    for (int i = 0; i < 2; i++)
#pragma unroll
        for (int j = 0; j < 8; j++)
#pragma unroll
            for (int e = 0; e < 4; e++) acc[i][j][e] = 0.f;

    const int warp = tid >> 5, lane = tid & 31;
    const int wm = warp & 3, wn = warp >> 2;

    int s = 0, fs = NSTG - 1;
    for (int kt = 0; kt < KT; ++kt) {
        asm volatile("cp.async.wait_group %0;" :: "n"(NSTG - 2));
        __syncthreads();

        compute_stage(Asm + s * A_ST, Bsm + s * B_ST, acc, wm, wn, lane);

        if (kt + NSTG - 1 < KT)
            fill_stage(A, strideA, B, ldb, m0, n0, kt + NSTG - 1,
                       Asm + fs * A_ST, Bsm + fs * B_ST, tid);
        asm volatile("cp.async.commit_group;");

        if (++s == NSTG) s = 0;
        if (++fs == NSTG) fs = 0;
    }

    // ---- epilogue ----
#pragma unroll
    for (int mi = 0; mi < 2; mi++)
#pragma unroll
        for (int ni = 0; ni < 8; ni++)
#pragma unroll
            for (int pp = 0; pp < 2; pp++) {
                int row = m0 + wm * 32 + mi * 16 + (lane >> 2) + pp * 8;
                int col = n0 + wn * 64 + ni * 8 + (lane & 3) * 2;
                float v0 = acc[mi][ni][2 * pp + 0] + bias[col];
                float v1 = acc[mi][ni][2 * pp + 1] + bias[col + 1];
                if constexpr (MODE == 0) {
                    v0 = v0 / (1.f + __expf(-v0));
                    v1 = v1 / (1.f + __expf(-v1));
                } else if constexpr (MODE == 1) {
                    __half2 g = *(const __half2*)(aux + (size_t)row * strideAux + col);
                    v0 *= __low2float(g);
                    v1 *= __high2float(g);
                } else if constexpr (MODE == 3) {
                    v0 = 0.5f * v0 * (1.f + erff(v0 * 0.70710678118654752f));
                    v1 = 0.5f * v1 * (1.f + erff(v1 * 0.70710678118654752f));
                }
                *(__half2*)((__half*)outp + (size_t)row * strideOut + col) =
                    __floats2half2_rn(v0, v1);
            }
}

// ---------------- kernel wrappers (up path) ----------------
__global__ __launch_bounds__(256, 2) void k_up1(const float* __restrict__ sb1) {
    gemm_core<0>(g_xh, C_DIM, g_sw1h, HS, sb1, nullptr, 0, g_H1, HS, C_DIM);
}
__global__ __launch_bounds__(256, 2) void k_up3(const float* __restrict__ sb3) {
    gemm_core<1>(g_xh, C_DIM, g_sw3h, HS, sb3, g_H1, HS, g_H2, HS, C_DIM);
}
// residue class r (= token mod 8), hash slot k: expert e = (3r + 7k) mod 8.
// A rows are token t = r + 8*j -> strided access, no gather needed.
__global__ __launch_bounds__(256, 2) void k_routed_up(const float* __restrict__ b1) {
    int z = blockIdx.z;                 // z = kk*8 + rr
    int rr = z & 7, kk = z >> 3;
    int e = (3 * rr + 7 * kk) & 7;
    gemm_core<3>(g_xh + rr * C_DIM, 8 * C_DIM,
                 g_w1h + (size_t)e * C_DIM * HR, HR,
                 b1 + e * HR, nullptr, 0,
                 g_Hr + (size_t)z * 4096 * HR, HR, C_DIM);
}

// ---------------- mega down kernel: out = 0.5*shared_down + 0.25*(y0+y1) ------
// One CTA accumulates three K-segments into the same registers:
//   seg0: H2[t] @ (0.5*sw2), K=2048  (A rows strided 8*HS, residue rr)
//   seg1: Hr[rr]     @ (0.25*w2[e0]), K=1024
//   seg2: Hr[8+rr]   @ (0.25*w2[e1]), K=1024
// Scales are pre-baked into g_sw2h/g_w2h at convert time. Single fp32 store.
#define KT_MEGA 128    // 64 + 32 + 32 iters of BK=32
__device__ __forceinline__ void mega_map(int kt, int rr, int e0, int e1,
                                         const __half*& Ap, int& sA, const __half*& Bp) {
    if (kt < 64) {
        Ap = g_H2 + (size_t)rr * HS + (size_t)kt * BK;
        sA = 8 * HS;
        Bp = g_sw2h + (size_t)kt * BK * C_DIM;
    } else if (kt < 96) {
        Ap = g_Hr + (size_t)rr * 4096 * HR + (size_t)(kt - 64) * BK;
        sA = HR;
        Bp = g_w2h + (size_t)e0 * HR * C_DIM + (size_t)(kt - 64) * BK * C_DIM;
    } else {
        Ap = g_Hr + (size_t)(8 + rr) * 4096 * HR + (size_t)(kt - 96) * BK;
        sA = HR;
        Bp = g_w2h + (size_t)e1 * HR * C_DIM + (size_t)(kt - 96) * BK * C_DIM;
    }
}
__device__ __forceinline__ void fill_stage_mega(
    int kt, int rr, int e0, int e1, int m0, int n0,
    __half* Asb, __half* Bsb, int tid)
{
    const __half* Ap; const __half* Bp; int sA;
    mega_map(kt, rr, e0, e1, Ap, sA, Bp);
#pragma unroll
    for (int i = 0; i < 2; i++) {
        int c = tid + i * 256;
        int ar = c >> 2, ac = c & 3;
        cp16(Asb + ar * ASTR + ac * 8,
             Ap + (size_t)(m0 + ar) * sA + ac * 8);
    }
#pragma unroll
    for (int i = 0; i < 2; i++) {
        int c = tid + i * 256;
        int br = c >> 4, bc = c & 15;
        cp16(Bsb + br * BSTR + bc * 8,
             Bp + (size_t)br * C_DIM + n0 + bc * 8);
    }
}
__global__ __launch_bounds__(256, 2) void k_down_mega(
    const float* __restrict__ sb2, const float* __restrict__ b2,
    float* __restrict__ dout)
{
    extern __shared__ __align__(16) __half smem[];
    __half* Asm = smem;
    __half* Bsm = smem + NSTG * A_ST;

    const int rr = blockIdx.z;
    const int e0 = (3 * rr) & 7;
    const int e1 = (3 * rr + 7) & 7;
    const int tid = threadIdx.x;
    const int m0 = blockIdx.y * BM;        // logical row j within residue class
    const int n0 = blockIdx.x * BN;

#pragma unroll
    for (int c = 0; c < NSTG - 1; c++) {
        fill_stage_mega(c, rr, e0, e1, m0, n0,
                        Asm + c * A_ST, Bsm + c * B_ST, tid);
        asm volatile("cp.async.commit_group;");
    }

    float acc[2][8][4];
#pragma unroll
    for (int i = 0; i < 2; i++)
#pragma unroll
        for (int j = 0; j < 8; j++)
#pragma unroll
            for (int e = 0; e < 4; e++) acc[i][j][e] = 0.f;

    const int warp = tid >> 5, lane = tid & 31;
    const int wm = warp & 3, wn = warp >> 2;

    int s = 0, fs = NSTG - 1;
    for (int kt = 0; kt < KT_MEGA; ++kt) {
        asm volatile("cp.async.wait_group %0;" :: "n"(NSTG - 2));
        __syncthreads();

        compute_stage(Asm + s * A_ST, Bsm + s * B_ST, acc, wm, wn, lane);

        if (kt + NSTG - 1 < KT_MEGA)
            fill_stage_mega(kt + NSTG - 1, rr, e0, e1, m0, n0,
                            Asm + fs * A_ST, Bsm + fs * B_ST, tid);
        asm volatile("cp.async.commit_group;");

        if (++s == NSTG) s = 0;
        if (++fs == NSTG) fs = 0;
    }

    // epilogue: single fp32 write, combined bias
#pragma unroll
    for (int mi = 0; mi < 2; mi++)
#pragma unroll
        for (int ni = 0; ni < 8; ni++)
#pragma unroll
            for (int pp = 0; pp < 2; pp++) {
                int rowl = m0 + wm * 32 + mi * 16 + (lane >> 2) + pp * 8;
                int col  = n0 + wn * 64 + ni * 8 + (lane & 3) * 2;
                float bb0 = 0.5f * sb2[col]
                          + 0.25f * (b2[e0 * C_DIM + col] + b2[e1 * C_DIM + col]);
                float bb1 = 0.5f * sb2[col + 1]
                          + 0.25f * (b2[e0 * C_DIM + col + 1] + b2[e1 * C_DIM + col + 1]);
                float2 f;
                f.x = acc[mi][ni][2 * pp + 0] + bb0;
                f.y = acc[mi][ni][2 * pp + 1] + bb1;
                size_t t = (size_t)rr + 8 * (size_t)rowl;    // actual token
                *(float2*)(dout + t * C_DIM + col) = f;
            }
}

// ---------------- launch ----------------
extern "C" void kernel_launch(void* const* d_in, const int* in_sizes, int n_in,
                              void* d_out, int out_size) {
    const float* x   = (const float*)d_in[0];
    // d_in[1] = t_emb : unused by reference
    const float* sw1 = (const float*)d_in[2];
    const float* sb1 = (const float*)d_in[3];
    const float* sw3 = (const float*)d_in[4];
    const float* sb3 = (const float*)d_in[5];
    const float* sw2 = (const float*)d_in[6];
    const float* sb2 = (const float*)d_in[7];
    const float* w1  = (const float*)d_in[8];
    const float* b1  = (const float*)d_in[9];
    const float* w2  = (const float*)d_in[10];
    const float* b2  = (const float*)d_in[11];
    float* out = (float*)d_out;

    cudaFuncSetAttribute(k_up1,       cudaFuncAttributeMaxDynamicSharedMemorySize, SMEM_BYTES);
    cudaFuncSetAttribute(k_up3,       cudaFuncAttributeMaxDynamicSharedMemorySize, SMEM_BYTES);
    cudaFuncSetAttribute(k_routed_up, cudaFuncAttributeMaxDynamicSharedMemorySize, SMEM_BYTES);
    cudaFuncSetAttribute(k_down_mega, cudaFuncAttributeMaxDynamicSharedMemorySize, SMEM_BYTES);

    // fp32 -> fp16 conversions; down-proj weights pre-scaled (0.5 shared, 0.25 routed)
    {
        struct { const float* p; int tag; int n; float sc; } cv[6] = {
            { x,   0, N_TOK * C_DIM,    1.0f  },
            { sw1, 1, C_DIM * HS,       1.0f  },
            { sw3, 2, C_DIM * HS,       1.0f  },
            { sw2, 3, HS * C_DIM,       0.5f  },
            { w1,  4, NE * C_DIM * HR,  1.0f  },
            { w2,  5, NE * HR * C_DIM,  0.25f },
        };
        for (int i = 0; i < 6; i++) {
            int n4 = cv[i].n / 4;
            k_convert<<<(n4 + 255) / 256, 256>>>(cv[i].p, cv[i].tag, n4, cv[i].sc);
        }
    }

    // up path
    k_up1<<<dim3(HS / BN, N_TOK / BM), 256, SMEM_BYTES>>>(sb1);
    k_up3<<<dim3(HS / BN, N_TOK / BM), 256, SMEM_BYTES>>>(sb3);
    k_routed_up<<<dim3(HR / BN, 4096 / BM, 16), 256, SMEM_BYTES>>>(b1);

    // fused down path: single pass, single out write
    k_down_mega<<<dim3(C_DIM / BN, 4096 / BM, 8), 256, SMEM_BYTES>>>(sb2, b2, out);
}

// round 9
// speedup vs baseline: 1.7681x; 1.0414x over previous
#include <cuda_runtime.h>
#include <cuda_fp16.h>
#include <stdint.h>
#include <math.h>

// ---------------- problem constants ----------------
#define N_TOK 32768      // B*T = 4*8192
#define C_DIM 1024
#define HS    2048
#define HR    1024
#define NE    8

// ---------------- GEMM tile config ----------------
#define BM 128
#define BN 128
#define BK 32
#define NSTG 5
#define ASTR (BK + 8)    // 40 halfs/row  (80B, conflict-free for ldmatrix)
#define BSTR (BN + 8)    // 136 halfs/row (272B, conflict-free for ldmatrix.trans)
#define A_ST (BM * ASTR)             // halfs per A stage (10240B)
#define B_ST (BK * BSTR)             // halfs per B stage (8704B)
#define SMEM_BYTES (NSTG * (A_ST + B_ST) * 2)   // 94720 B

// ---------------- static scratch (no allocations allowed) ----------------
__device__ __half g_xh[N_TOK * C_DIM];          // x in fp16
__device__ __half g_sw1h[C_DIM * HS];
__device__ __half g_sw3h[C_DIM * HS];
__device__ __half g_sw2h[HS * C_DIM];           // pre-scaled by 0.5
__device__ __half g_w1h[NE * C_DIM * HR];
__device__ __half g_w2h[NE * HR * C_DIM];       // pre-scaled by 0.25
__device__ __half g_H2[N_TOK * HS];             // silu(x@sw1+b1) * (x@sw3+b3)
__device__ __half g_Hr[2 * N_TOK * HR];         // routed hidden, grouped [k][r][4096][HR]

// ---------------- small PTX helpers ----------------
__device__ __forceinline__ void cp16(void* s, const void* g) {
    unsigned sa = (unsigned)__cvta_generic_to_shared(s);
    asm volatile("cp.async.cg.shared.global [%0], [%1], 16;" :: "r"(sa), "l"(g));
}
__device__ __forceinline__ void ldsm4(uint32_t* r, const __half* p) {
    unsigned a = (unsigned)__cvta_generic_to_shared(p);
    asm volatile("ldmatrix.sync.aligned.m8n8.x4.shared.b16 {%0,%1,%2,%3}, [%4];"
                 : "=r"(r[0]), "=r"(r[1]), "=r"(r[2]), "=r"(r[3]) : "r"(a));
}
__device__ __forceinline__ void ldsm4t(uint32_t* r, const __half* p) {
    unsigned a = (unsigned)__cvta_generic_to_shared(p);
    asm volatile("ldmatrix.sync.aligned.m8n8.x4.trans.shared.b16 {%0,%1,%2,%3}, [%4];"
                 : "=r"(r[0]), "=r"(r[1]), "=r"(r[2]), "=r"(r[3]) : "r"(a));
}
__device__ __forceinline__ void mma16816(float* d, const uint32_t* a, const uint32_t* b) {
    asm volatile(
        "mma.sync.aligned.m16n8k16.row.col.f32.f16.f16.f32 "
        "{%0,%1,%2,%3},{%4,%5,%6,%7},{%8,%9},{%0,%1,%2,%3};"
        : "+f"(d[0]), "+f"(d[1]), "+f"(d[2]), "+f"(d[3])
        : "r"(a[0]), "r"(a[1]), "r"(a[2]), "r"(a[3]), "r"(b[0]), "r"(b[1]));
}

// ---------------- conversion kernels (fp32 -> fp16, vectorized x4, scaled) ----------
__device__ __forceinline__ __half* conv_dst(int tag) {
    switch (tag) {
        case 0: return g_xh;
        case 3: return g_sw2h;
        case 4: return g_w1h;
        default: return g_w2h;
    }
}
__global__ void k_convert(const float* __restrict__ src, int tag, int n4, float scale) {
    int i = blockIdx.x * blockDim.x + threadIdx.x;
    if (i >= n4) return;
    float4 v = ((const float4*)src)[i];
    __half2* d = (__half2*)conv_dst(tag);
    d[2 * i]     = __floats2half2_rn(v.x * scale, v.y * scale);
    d[2 * i + 1] = __floats2half2_rn(v.z * scale, v.w * scale);
}
// sw1 + sw3 in one launch (keeps total pre-GEMM launches at 5 so ncu -s 5 hits the GEMM)
__global__ void k_convert13(const float* __restrict__ s1, const float* __restrict__ s3, int n4) {
    int i = blockIdx.x * blockDim.x + threadIdx.x;
    const float* src; __half2* d;
    if (i < n4)           { src = s1; d = (__half2*)g_sw1h; }
    else if (i < 2 * n4)  { src = s3; d = (__half2*)g_sw3h; i -= n4; }
    else return;
    float4 v = ((const float4*)src)[i];
    d[2 * i]     = __floats2half2_rn(v.x, v.y);
    d[2 * i + 1] = __floats2half2_rn(v.z, v.w);
}

// ---------------- generic stage fill (cp.async) ----------------
__device__ __forceinline__ void fill_stage(
    const __half* __restrict__ A, int strideA,
    const __half* __restrict__ B, int ldb,
    int m0, int n0, int kt, __half* Asb, __half* Bsb, int tid)
{
#pragma unroll
    for (int i = 0; i < 2; i++) {              // A: 128x32 halfs = 512 x 16B chunks
        int c = tid + i * 256;
        int ar = c >> 2, ac = c & 3;
        cp16(Asb + ar * ASTR + ac * 8,
             A + (size_t)(m0 + ar) * strideA + kt * BK + ac * 8);
    }
#pragma unroll
    for (int i = 0; i < 2; i++) {              // B: 32x128 halfs = 512 x 16B chunks
        int c = tid + i * 256;
        int br = c >> 4, bc = c & 15;
        cp16(Bsb + br * BSTR + bc * 8,
             B + (size_t)(kt * BK + br) * ldb + n0 + bc * 8);
    }
}

// ---------------- warp-tile compute on one resident stage (128x128) ----------------
__device__ __forceinline__ void compute_stage(
    const __half* As, const __half* Bs, float acc[2][8][4],
    int wm, int wn, int lane)
{
#pragma unroll
    for (int ks = 0; ks < 2; ks++) {           // two k16 steps per BK=32
        uint32_t a[2][4];
#pragma unroll
        for (int mi = 0; mi < 2; mi++) {
            const __half* p = &As[(wm * 32 + mi * 16 + (lane & 15)) * ASTR
                                  + ks * 16 + (lane >> 4) * 8];
            ldsm4(a[mi], p);
        }
#pragma unroll
        for (int p4 = 0; p4 < 4; p4++) {       // 16 cols per ldmatrix.x4.trans
            uint32_t b[4];
            const __half* p = &Bs[(ks * 16 + (lane & 7) + ((lane >> 3) & 1) * 8) * BSTR
                                  + wn * 64 + p4 * 16 + (lane >> 4) * 8];
            ldsm4t(b, p);
            mma16816(acc[0][2 * p4 + 0], a[0], &b[0]);
            mma16816(acc[0][2 * p4 + 1], a[0], &b[2]);
            mma16816(acc[1][2 * p4 + 0], a[1], &b[0]);
            mma16816(acc[1][2 * p4 + 1], a[1], &b[2]);
        }
    }
}

// ================= fused shared-up kernel: H2 = silu(x@sw1+b1)*(x@sw3+b3) ======
// CTA tile: 128 rows x 64 H2-cols, BOTH branches. B stage rows hold
// [sw1 cols 0..63 | sw3 cols 0..63] in the same 136-half-stride layout.
__device__ __forceinline__ void fill_stage_up(
    int kt, int m0, int n0, __half* Asb, __half* Bsb, int tid)
{
#pragma unroll
    for (int i = 0; i < 2; i++) {              // A: 128x32 halfs
        int c = tid + i * 256;
        int ar = c >> 2, ac = c & 3;
        cp16(Asb + ar * ASTR + ac * 8,
             g_xh + (size_t)(m0 + ar) * C_DIM + kt * BK + ac * 8);
    }
    int br = tid >> 3, bc = tid & 7;           // 32 rows x 8 chunks per branch
    cp16(Bsb + br * BSTR + bc * 8,
         g_sw1h + (size_t)(kt * BK + br) * HS + n0 + bc * 8);
    cp16(Bsb + br * BSTR + 64 + bc * 8,
         g_sw3h + (size_t)(kt * BK + br) * HS + n0 + bc * 8);
}

__global__ __launch_bounds__(256, 2) void k_up_fused(
    const float* __restrict__ sb1, const float* __restrict__ sb3)
{
    extern __shared__ __align__(16) __half smem[];
    __half* Asm = smem;
    __half* Bsm = smem + NSTG * A_ST;

    const int tid = threadIdx.x;
    const int m0 = blockIdx.y * BM;
    const int n0 = blockIdx.x * 64;
    const int KT = C_DIM / BK;                 // 32

#pragma unroll
    for (int c = 0; c < NSTG - 1; c++) {
        fill_stage_up(c, m0, n0, Asm + c * A_ST, Bsm + c * B_ST, tid);
        asm volatile("cp.async.commit_group;");
    }

    float acc1[2][4][4], acc3[2][4][4];
#pragma unroll
    for (int i = 0; i < 2; i++)
#pragma unroll
        for (int j = 0; j < 4; j++)
#pragma unroll
            for (int e = 0; e < 4; e++) { acc1[i][j][e] = 0.f; acc3[i][j][e] = 0.f; }

    const int warp = tid >> 5, lane = tid & 31;
    const int wm = warp & 3, wn = (warp >> 2) & 1;   // warp tile: 32 rows x 32 cols/branch

    int s = 0, fs = NSTG - 1;
    for (int kt = 0; kt < KT; ++kt) {
        asm volatile("cp.async.wait_group %0;" :: "n"(NSTG - 2));
        __syncthreads();

        const __half* As = Asm + s * A_ST;
        const __half* Bs = Bsm + s * B_ST;
#pragma unroll
        for (int ks = 0; ks < 2; ks++) {
            uint32_t a[2][4];
#pragma unroll
            for (int mi = 0; mi < 2; mi++) {
                const __half* p = &As[(wm * 32 + mi * 16 + (lane & 15)) * ASTR
                                      + ks * 16 + (lane >> 4) * 8];
                ldsm4(a[mi], p);
            }
            const int brow = (ks * 16 + (lane & 7) + ((lane >> 3) & 1) * 8) * BSTR
                             + (lane >> 4) * 8;
#pragma unroll
            for (int p4 = 0; p4 < 2; p4++) {   // branch 1 (sw1): cols wn*32 + p4*16
                uint32_t b[4];
                ldsm4t(b, &Bs[brow + wn * 32 + p4 * 16]);
                mma16816(acc1[0][2 * p4 + 0], a[0], &b[0]);
                mma16816(acc1[0][2 * p4 + 1], a[0], &b[2]);
                mma16816(acc1[1][2 * p4 + 0], a[1], &b[0]);
                mma16816(acc1[1][2 * p4 + 1], a[1], &b[2]);
            }
#pragma unroll
            for (int p4 = 0; p4 < 2; p4++) {   // branch 3 (sw3): +64 col offset
                uint32_t b[4];
                ldsm4t(b, &Bs[brow + 64 + wn * 32 + p4 * 16]);
                mma16816(acc3[0][2 * p4 + 0], a[0], &b[0]);
                mma16816(acc3[0][2 * p4 + 1], a[0], &b[2]);
                mma16816(acc3[1][2 * p4 + 0], a[1], &b[0]);
                mma16816(acc3[1][2 * p4 + 1], a[1], &b[2]);
            }
        }

        if (kt + NSTG - 1 < KT)
            fill_stage_up(kt + NSTG - 1, m0, n0,
                          Asm + fs * A_ST, Bsm + fs * B_ST, tid);
        asm volatile("cp.async.commit_group;");

        if (++s == NSTG) s = 0;
        if (++fs == NSTG) fs = 0;
    }

    // epilogue: H2 = silu(v1) * v3, fp16 store
#pragma unroll
    for (int mi = 0; mi < 2; mi++)
#pragma unroll
        for (int ni = 0; ni < 4; ni++)
#pragma unroll
            for (int pp = 0; pp < 2; pp++) {
                int row = m0 + wm * 32 + mi * 16 + (lane >> 2) + pp * 8;
                int col = n0 + wn * 32 + ni * 8 + (lane & 3) * 2;
                float u0 = acc1[mi][ni][2 * pp + 0] + sb1[col];
                float u1 = acc1[mi][ni][2 * pp + 1] + sb1[col + 1];
                float w0 = acc3[mi][ni][2 * pp + 0] + sb3[col];
                float w1 = acc3[mi][ni][2 * pp + 1] + sb3[col + 1];
                float v0 = u0 / (1.f + __expf(-u0)) * w0;
                float v1 = u1 / (1.f + __expf(-u1)) * w1;
                *(__half2*)(g_H2 + (size_t)row * HS + col) = __floats2half2_rn(v0, v1);
            }
}

// ---------------- routed up (gelu) ----------------
__device__ __forceinline__ void gemm_routed_up(
    const __half* __restrict__ A, int strideA,
    const __half* __restrict__ B,
    const float* __restrict__ bias,
    __half* __restrict__ outp)
{
    extern __shared__ __align__(16) __half smem[];
    __half* Asm = smem;
    __half* Bsm = smem + NSTG * A_ST;

    const int tid = threadIdx.x;
    const int m0 = blockIdx.y * BM;
    const int n0 = blockIdx.x * BN;
    const int KT = C_DIM / BK;

#pragma unroll
    for (int c = 0; c < NSTG - 1; c++) {
        fill_stage(A, strideA, B, HR, m0, n0, c,
                   Asm + c * A_ST, Bsm + c * B_ST, tid);
        asm volatile("cp.async.commit_group;");
    }

    float acc[2][8][4];
#pragma unroll
    for (int i = 0; i < 2; i++)
#pragma unroll
        for (int j = 0; j < 8; j++)
#pragma unroll
            for (int e = 0; e < 4; e++) acc[i][j][e] = 0.f;

    const int warp = tid >> 5, lane = tid & 31;
    const int wm = warp & 3, wn = warp >> 2;

    int s = 0, fs = NSTG - 1;
    for (int kt = 0; kt < KT; ++kt) {
        asm volatile("cp.async.wait_group %0;" :: "n"(NSTG - 2));
        __syncthreads();

        compute_stage(Asm + s * A_ST, Bsm + s * B_ST, acc, wm, wn, lane);

        if (kt + NSTG - 1 < KT)
            fill_stage(A, strideA, B, HR, m0, n0, kt + NSTG - 1,
                       Asm + fs * A_ST, Bsm + fs * B_ST, tid);
        asm volatile("cp.async.commit_group;");

        if (++s == NSTG) s = 0;
        if (++fs == NSTG) fs = 0;
    }

#pragma unroll
    for (int mi = 0; mi < 2; mi++)
#pragma unroll
        for (int ni = 0; ni < 8; ni++)
#pragma unroll
            for (int pp = 0; pp < 2; pp++) {
                int row = m0 + wm * 32 + mi * 16 + (lane >> 2) + pp * 8;
                int col = n0 + wn * 64 + ni * 8 + (lane & 3) * 2;
                float v0 = acc[mi][ni][2 * pp + 0] + bias[col];
                float v1 = acc[mi][ni][2 * pp + 1] + bias[col + 1];
                v0 = 0.5f * v0 * (1.f + erff(v0 * 0.70710678118654752f));
                v1 = 0.5f * v1 * (1.f + erff(v1 * 0.70710678118654752f));
                *(__half2*)(outp + (size_t)row * HR + col) = __floats2half2_rn(v0, v1);
            }
}
// residue class r (= token mod 8), hash slot k: expert e = (3r + 7k) mod 8.
// A rows are token t = r + 8*j -> strided access, no gather needed.
__global__ __launch_bounds__(256, 2) void k_routed_up(const float* __restrict__ b1) {
    int z = blockIdx.z;                 // z = kk*8 + rr
    int rr = z & 7, kk = z >> 3;
    int e = (3 * rr + 7 * kk) & 7;
    gemm_routed_up(g_xh + rr * C_DIM, 8 * C_DIM,
                   g_w1h + (size_t)e * C_DIM * HR,
                   b1 + e * HR,
                   g_Hr + (size_t)z * 4096 * HR);
}

// ---------------- mega down kernel: out = 0.5*shared_down + 0.25*(y0+y1) ------
// Three K-segments accumulated into the same registers:
//   seg0: H2[t] @ (0.5*sw2), K=2048  (A rows strided 8*HS, residue rr)
//   seg1: Hr[rr]   @ (0.25*w2[e0]), K=1024
//   seg2: Hr[8+rr] @ (0.25*w2[e1]), K=1024
// Scales pre-baked into g_sw2h/g_w2h at convert time. Single fp32 store.
#define KT_MEGA 128    // 64 + 32 + 32 iters of BK=32
__device__ __forceinline__ void mega_map(int kt, int rr, int e0, int e1,
                                         const __half*& Ap, int& sA, const __half*& Bp) {
    if (kt < 64) {
        Ap = g_H2 + (size_t)rr * HS + (size_t)kt * BK;
        sA = 8 * HS;
        Bp = g_sw2h + (size_t)kt * BK * C_DIM;
    } else if (kt < 96) {
        Ap = g_Hr + (size_t)rr * 4096 * HR + (size_t)(kt - 64) * BK;
        sA = HR;
        Bp = g_w2h + (size_t)e0 * HR * C_DIM + (size_t)(kt - 64) * BK * C_DIM;
    } else {
        Ap = g_Hr + (size_t)(8 + rr) * 4096 * HR + (size_t)(kt - 96) * BK;
        sA = HR;
        Bp = g_w2h + (size_t)e1 * HR * C_DIM + (size_t)(kt - 96) * BK * C_DIM;
    }
}
__device__ __forceinline__ void fill_stage_mega(
    int kt, int rr, int e0, int e1, int m0, int n0,
    __half* Asb, __half* Bsb, int tid)
{
    const __half* Ap; const __half* Bp; int sA;
    mega_map(kt, rr, e0, e1, Ap, sA, Bp);
#pragma unroll
    for (int i = 0; i < 2; i++) {
        int c = tid + i * 256;
        int ar = c >> 2, ac = c & 3;
        cp16(Asb + ar * ASTR + ac * 8,
             Ap + (size_t)(m0 + ar) * sA + ac * 8);
    }
#pragma unroll
    for (int i = 0; i < 2; i++) {
        int c = tid + i * 256;
        int br = c >> 4, bc = c & 15;
        cp16(Bsb + br * BSTR + bc * 8,
             Bp + (size_t)br * C_DIM + n0 + bc * 8);
    }
}
__global__ __launch_bounds__(256, 2) void k_down_mega(
    const float* __restrict__ sb2, const float* __restrict__ b2,
    float* __restrict__ dout)
{
    extern __shared__ __align__(16) __half smem[];
    __half* Asm = smem;
    __half* Bsm = smem + NSTG * A_ST;

    const int rr = blockIdx.z;
    const int e0 = (3 * rr) & 7;
    const int e1 = (3 * rr + 7) & 7;
    const int tid = threadIdx.x;
    const int m0 = blockIdx.y * BM;        // logical row j within residue class
    const int n0 = blockIdx.x * BN;

#pragma unroll
    for (int c = 0; c < NSTG - 1; c++) {
        fill_stage_mega(c, rr, e0, e1, m0, n0,
                        Asm + c * A_ST, Bsm + c * B_ST, tid);
        asm volatile("cp.async.commit_group;");
    }

    float acc[2][8][4];
#pragma unroll
    for (int i = 0; i < 2; i++)
#pragma unroll
        for (int j = 0; j < 8; j++)
#pragma unroll
            for (int e = 0; e < 4; e++) acc[i][j][e] = 0.f;

    const int warp = tid >> 5, lane = tid & 31;
    const int wm = warp & 3, wn = warp >> 2;

    int s = 0, fs = NSTG - 1;
    for (int kt = 0; kt < KT_MEGA; ++kt) {
        asm volatile("cp.async.wait_group %0;" :: "n"(NSTG - 2));
        __syncthreads();

        compute_stage(Asm + s * A_ST, Bsm + s * B_ST, acc, wm, wn, lane);

        if (kt + NSTG - 1 < KT_MEGA)
            fill_stage_mega(kt + NSTG - 1, rr, e0, e1, m0, n0,
                            Asm + fs * A_ST, Bsm + fs * B_ST, tid);
        asm volatile("cp.async.commit_group;");

        if (++s == NSTG) s = 0;
        if (++fs == NSTG) fs = 0;
    }

    // epilogue: single fp32 write, combined bias
#pragma unroll
    for (int mi = 0; mi < 2; mi++)
#pragma unroll
        for (int ni = 0; ni < 8; ni++)
#pragma unroll
            for (int pp = 0; pp < 2; pp++) {
                int rowl = m0 + wm * 32 + mi * 16 + (lane >> 2) + pp * 8;
                int col  = n0 + wn * 64 + ni * 8 + (lane & 3) * 2;
                float bb0 = 0.5f * sb2[col]
                          + 0.25f * (b2[e0 * C_DIM + col] + b2[e1 * C_DIM + col]);
                float bb1 = 0.5f * sb2[col + 1]
                          + 0.25f * (b2[e0 * C_DIM + col + 1] + b2[e1 * C_DIM + col + 1]);
                float2 f;
                f.x = acc[mi][ni][2 * pp + 0] + bb0;
                f.y = acc[mi][ni][2 * pp + 1] + bb1;
                size_t t = (size_t)rr + 8 * (size_t)rowl;    // actual token
                *(float2*)(dout + t * C_DIM + col) = f;
            }
}

// ---------------- launch ----------------
extern "C" void kernel_launch(void* const* d_in, const int* in_sizes, int n_in,
                              void* d_out, int out_size) {
    const float* x   = (const float*)d_in[0];
    // d_in[1] = t_emb : unused by reference
    const float* sw1 = (const float*)d_in[2];
    const float* sb1 = (const float*)d_in[3];
    const float* sw3 = (const float*)d_in[4];
    const float* sb3 = (const float*)d_in[5];
    const float* sw2 = (const float*)d_in[6];
    const float* sb2 = (const float*)d_in[7];
    const float* w1  = (const float*)d_in[8];
    const float* b1  = (const float*)d_in[9];
    const float* w2  = (const float*)d_in[10];
    const float* b2  = (const float*)d_in[11];
    float* out = (float*)d_out;

    cudaFuncSetAttribute(k_up_fused,  cudaFuncAttributeMaxDynamicSharedMemorySize, SMEM_BYTES);
    cudaFuncSetAttribute(k_routed_up, cudaFuncAttributeMaxDynamicSharedMemorySize, SMEM_BYTES);
    cudaFuncSetAttribute(k_down_mega, cudaFuncAttributeMaxDynamicSharedMemorySize, SMEM_BYTES);

    // fp32 -> fp16 conversions (5 launches, so the GEMM is ncu launch #6);
    // down-proj weights pre-scaled (0.5 shared, 0.25 routed)
    {
        int n4x = (N_TOK * C_DIM) / 4;
        k_convert<<<(n4x + 255) / 256, 256>>>(x, 0, n4x, 1.0f);
        int n4w = (C_DIM * HS) / 4;
        k_convert13<<<(2 * n4w + 255) / 256, 256>>>(sw1, sw3, n4w);
        k_convert<<<(n4w + 255) / 256, 256>>>(sw2, 3, n4w, 0.5f);
        int n4e = (NE * C_DIM * HR) / 4;
        k_convert<<<(n4e + 255) / 256, 256>>>(w1, 4, n4e, 1.0f);
        k_convert<<<(n4e + 255) / 256, 256>>>(w2, 5, n4e, 0.25f);
    }

    // fused shared up path: writes H2 directly (no H1 intermediate)
    k_up_fused<<<dim3(HS / 64, N_TOK / BM), 256, SMEM_BYTES>>>(sb1, sb3);

    // routed up
    k_routed_up<<<dim3(HR / BN, 4096 / BM, 16), 256, SMEM_BYTES>>>(b1);

    // fused down path: single pass, single out write
    k_down_mega<<<dim3(C_DIM / BN, 4096 / BM, 8), 256, SMEM_BYTES>>>(sb2, b2, out);
}

// round 10
// speedup vs baseline: 1.9021x; 1.0758x over previous
#include <cuda_runtime.h>
#include <cuda_fp16.h>
#include <stdint.h>
#include <math.h>

// ---------------- problem constants ----------------
#define N_TOK 32768      // B*T = 4*8192
#define C_DIM 1024
#define HS    2048
#define HR    1024
#define NE    8

// ---------------- GEMM tile config ----------------
#define BM 128
#define BN 128
#define BK 64
#define NSTG 3
#define ASTR (BK + 8)    // 72 halfs/row (144B; rows 0..7 -> banks 4r..4r+3, conflict-free)
#define BSTR (BN + 8)    // 136 halfs/row (272B, conflict-free for ldmatrix.trans)
#define A_ST (BM * ASTR)             // 9216 halfs per A stage
#define B_ST (BK * BSTR)             // 8704 halfs per B stage
#define SMEM_BYTES (NSTG * (A_ST + B_ST) * 2)   // 107520 B -> 2 CTAs/SM = 215KB

// ---------------- static scratch (no allocations allowed) ----------------
__device__ __half g_xh[N_TOK * C_DIM];          // x in fp16
__device__ __half g_sw1h[C_DIM * HS];
__device__ __half g_sw3h[C_DIM * HS];
__device__ __half g_sw2h[HS * C_DIM];           // pre-scaled by 0.5
__device__ __half g_w1h[NE * C_DIM * HR];
__device__ __half g_w2h[NE * HR * C_DIM];       // pre-scaled by 0.25
__device__ __half g_H2[N_TOK * HS];             // silu(x@sw1+b1) * (x@sw3+b3)
__device__ __half g_Hr[2 * N_TOK * HR];         // routed hidden, grouped [k][r][4096][HR]

// ---------------- small PTX helpers ----------------
__device__ __forceinline__ void cp16(void* s, const void* g) {
    unsigned sa = (unsigned)__cvta_generic_to_shared(s);
    asm volatile("cp.async.cg.shared.global [%0], [%1], 16;" :: "r"(sa), "l"(g));
}
__device__ __forceinline__ void ldsm4(uint32_t* r, const __half* p) {
    unsigned a = (unsigned)__cvta_generic_to_shared(p);
    asm volatile("ldmatrix.sync.aligned.m8n8.x4.shared.b16 {%0,%1,%2,%3}, [%4];"
                 : "=r"(r[0]), "=r"(r[1]), "=r"(r[2]), "=r"(r[3]) : "r"(a));
}
__device__ __forceinline__ void ldsm4t(uint32_t* r, const __half* p) {
    unsigned a = (unsigned)__cvta_generic_to_shared(p);
    asm volatile("ldmatrix.sync.aligned.m8n8.x4.trans.shared.b16 {%0,%1,%2,%3}, [%4];"
                 : "=r"(r[0]), "=r"(r[1]), "=r"(r[2]), "=r"(r[3]) : "r"(a));
}
__device__ __forceinline__ void mma16816(float* d, const uint32_t* a, const uint32_t* b) {
    asm volatile(
        "mma.sync.aligned.m16n8k16.row.col.f32.f16.f16.f32 "
        "{%0,%1,%2,%3},{%4,%5,%6,%7},{%8,%9},{%0,%1,%2,%3};"
        : "+f"(d[0]), "+f"(d[1]), "+f"(d[2]), "+f"(d[3])
        : "r"(a[0]), "r"(a[1]), "r"(a[2]), "r"(a[3]), "r"(b[0]), "r"(b[1]));
}

// ---------------- conversion kernels (fp32 -> fp16, vectorized x4, scaled) ----------
__device__ __forceinline__ __half* conv_dst(int tag) {
    switch (tag) {
        case 0: return g_xh;
        case 3: return g_sw2h;
        case 4: return g_w1h;
        default: return g_w2h;
    }
}
__global__ void k_convert(const float* __restrict__ src, int tag, int n4, float scale) {
    int i = blockIdx.x * blockDim.x + threadIdx.x;
    if (i >= n4) return;
    float4 v = ((const float4*)src)[i];
    __half2* d = (__half2*)conv_dst(tag);
    d[2 * i]     = __floats2half2_rn(v.x * scale, v.y * scale);
    d[2 * i + 1] = __floats2half2_rn(v.z * scale, v.w * scale);
}
__global__ void k_convert13(const float* __restrict__ s1, const float* __restrict__ s3, int n4) {
    int i = blockIdx.x * blockDim.x + threadIdx.x;
    const float* src; __half2* d;
    if (i < n4)           { src = s1; d = (__half2*)g_sw1h; }
    else if (i < 2 * n4)  { src = s3; d = (__half2*)g_sw3h; i -= n4; }
    else return;
    float4 v = ((const float4*)src)[i];
    d[2 * i]     = __floats2half2_rn(v.x, v.y);
    d[2 * i + 1] = __floats2half2_rn(v.z, v.w);
}

// ---------------- generic stage fill (BK=64, cp.async) ----------------
__device__ __forceinline__ void fill_stage(
    const __half* __restrict__ A, int strideA,
    const __half* __restrict__ B, int ldb,
    int m0, int n0, int kt, __half* Asb, __half* Bsb, int tid)
{
#pragma unroll
    for (int i = 0; i < 4; i++) {              // A: 128x64 halfs = 1024 x 16B chunks
        int c = tid + i * 256;
        int ar = c >> 3, ac = c & 7;
        cp16(Asb + ar * ASTR + ac * 8,
             A + (size_t)(m0 + ar) * strideA + kt * BK + ac * 8);
    }
#pragma unroll
    for (int i = 0; i < 4; i++) {              // B: 64x128 halfs = 1024 x 16B chunks
        int c = tid + i * 256;
        int br = c >> 4, bc = c & 15;
        cp16(Bsb + br * BSTR + bc * 8,
             B + (size_t)(kt * BK + br) * ldb + n0 + bc * 8);
    }
}

// ---------------- warp-tile compute on one resident stage (128x128, BK=64) ----------
__device__ __forceinline__ void compute_stage(
    const __half* As, const __half* Bs, float acc[2][8][4],
    int wm, int wn, int lane)
{
#pragma unroll
    for (int ks = 0; ks < 4; ks++) {           // four k16 steps per BK=64
        uint32_t a[2][4];
#pragma unroll
        for (int mi = 0; mi < 2; mi++) {
            const __half* p = &As[(wm * 32 + mi * 16 + (lane & 15)) * ASTR
                                  + ks * 16 + (lane >> 4) * 8];
            ldsm4(a[mi], p);
        }
#pragma unroll
        for (int p4 = 0; p4 < 4; p4++) {       // 16 cols per ldmatrix.x4.trans
            uint32_t b[4];
            const __half* p = &Bs[(ks * 16 + (lane & 7) + ((lane >> 3) & 1) * 8) * BSTR
                                  + wn * 64 + p4 * 16 + (lane >> 4) * 8];
            ldsm4t(b, p);
            mma16816(acc[0][2 * p4 + 0], a[0], &b[0]);
            mma16816(acc[0][2 * p4 + 1], a[0], &b[2]);
            mma16816(acc[1][2 * p4 + 0], a[1], &b[0]);
            mma16816(acc[1][2 * p4 + 1], a[1], &b[2]);
        }
    }
}

// ---------------- up-fused stage fill: A=x, B=[sw1 64cols | sw3 64cols] ----------
__device__ __forceinline__ void fill_stage_up(
    int kt, int m0, int n0, __half* Asb, __half* Bsb, int tid)
{
#pragma unroll
    for (int i = 0; i < 4; i++) {              // A: 128x64 halfs
        int c = tid + i * 256;
        int ar = c >> 3, ac = c & 7;
        cp16(Asb + ar * ASTR + ac * 8,
             g_xh + (size_t)(m0 + ar) * C_DIM + kt * BK + ac * 8);
    }
#pragma unroll
    for (int i = 0; i < 4; i++) {              // B: 64 rows x (64|64) halfs
        int c = tid + i * 256;
        int br = c >> 4, bc = c & 15;
        if (bc < 8)
            cp16(Bsb + br * BSTR + bc * 8,
                 g_sw1h + (size_t)(kt * BK + br) * HS + n0 + bc * 8);
        else
            cp16(Bsb + br * BSTR + 64 + (bc - 8) * 8,
                 g_sw3h + (size_t)(kt * BK + br) * HS + n0 + (bc - 8) * 8);
    }
}

// ================= merged UP kernel ==========================================
// 1D grid, 12288 CTAs:
//   bid < 8192 : shared-up tile (128 rows x 64 H2-cols, both branches)
//   bid >= 8192: routed-up tile (128x128, gelu), z = expert-slot group
__global__ __launch_bounds__(256, 2) void k_up_all(
    const float* __restrict__ sb1, const float* __restrict__ sb3,
    const float* __restrict__ b1)
{
    extern __shared__ __align__(16) __half smem[];
    __half* Asm = smem;
    __half* Bsm = smem + NSTG * A_ST;

    const int tid = threadIdx.x;
    const int bid = blockIdx.x;
    const int warp = tid >> 5, lane = tid & 31;
    const int KT = C_DIM / BK;                 // 16

    if (bid < 8192) {
        // ---------- shared up: H2 = silu(x@sw1+b1)*(x@sw3+b3) ----------
        const int m0 = (bid >> 5) * BM;
        const int n0 = (bid & 31) * 64;
        const int wm = warp & 3, wn = (warp >> 2) & 1;

#pragma unroll
        for (int c = 0; c < NSTG - 1; c++) {
            fill_stage_up(c, m0, n0, Asm + c * A_ST, Bsm + c * B_ST, tid);
            asm volatile("cp.async.commit_group;");
        }

        float acc1[2][4][4], acc3[2][4][4];
#pragma unroll
        for (int i = 0; i < 2; i++)
#pragma unroll
            for (int j = 0; j < 4; j++)
#pragma unroll
                for (int e = 0; e < 4; e++) { acc1[i][j][e] = 0.f; acc3[i][j][e] = 0.f; }

        int s = 0, fs = NSTG - 1;
        for (int kt = 0; kt < KT; ++kt) {
            asm volatile("cp.async.wait_group %0;" :: "n"(NSTG - 2));
            __syncthreads();

            const __half* As = Asm + s * A_ST;
            const __half* Bs = Bsm + s * B_ST;
#pragma unroll
            for (int ks = 0; ks < 4; ks++) {
                uint32_t a[2][4];
#pragma unroll
                for (int mi = 0; mi < 2; mi++) {
                    const __half* p = &As[(wm * 32 + mi * 16 + (lane & 15)) * ASTR
                                          + ks * 16 + (lane >> 4) * 8];
                    ldsm4(a[mi], p);
                }
                const int brow = (ks * 16 + (lane & 7) + ((lane >> 3) & 1) * 8) * BSTR
                                 + (lane >> 4) * 8;
#pragma unroll
                for (int p4 = 0; p4 < 2; p4++) {   // branch 1 (sw1)
                    uint32_t b[4];
                    ldsm4t(b, &Bs[brow + wn * 32 + p4 * 16]);
                    mma16816(acc1[0][2 * p4 + 0], a[0], &b[0]);
                    mma16816(acc1[0][2 * p4 + 1], a[0], &b[2]);
                    mma16816(acc1[1][2 * p4 + 0], a[1], &b[0]);
                    mma16816(acc1[1][2 * p4 + 1], a[1], &b[2]);
                }
#pragma unroll
                for (int p4 = 0; p4 < 2; p4++) {   // branch 3 (sw3): +64 col offset
                    uint32_t b[4];
                    ldsm4t(b, &Bs[brow + 64 + wn * 32 + p4 * 16]);
                    mma16816(acc3[0][2 * p4 + 0], a[0], &b[0]);
                    mma16816(acc3[0][2 * p4 + 1], a[0], &b[2]);
                    mma16816(acc3[1][2 * p4 + 0], a[1], &b[0]);
                    mma16816(acc3[1][2 * p4 + 1], a[1], &b[2]);
                }
            }

            if (kt + NSTG - 1 < KT)
                fill_stage_up(kt + NSTG - 1, m0, n0,
                              Asm + fs * A_ST, Bsm + fs * B_ST, tid);
            asm volatile("cp.async.commit_group;");

            if (++s == NSTG) s = 0;
            if (++fs == NSTG) fs = 0;
        }

#pragma unroll
        for (int mi = 0; mi < 2; mi++)
#pragma unroll
            for (int ni = 0; ni < 4; ni++)
#pragma unroll
                for (int pp = 0; pp < 2; pp++) {
                    int row = m0 + wm * 32 + mi * 16 + (lane >> 2) + pp * 8;
                    int col = n0 + wn * 32 + ni * 8 + (lane & 3) * 2;
                    float u0 = acc1[mi][ni][2 * pp + 0] + sb1[col];
                    float u1 = acc1[mi][ni][2 * pp + 1] + sb1[col + 1];
                    float w0 = acc3[mi][ni][2 * pp + 0] + sb3[col];
                    float w1 = acc3[mi][ni][2 * pp + 1] + sb3[col + 1];
                    float v0 = u0 / (1.f + __expf(-u0)) * w0;
                    float v1 = u1 / (1.f + __expf(-u1)) * w1;
                    *(__half2*)(g_H2 + (size_t)row * HS + col) = __floats2half2_rn(v0, v1);
                }
    } else {
        // ---------- routed up: Hr[z] = gelu(x_r @ w1[e] + b1[e]) ----------
        const int rid = bid - 8192;
        const int z = rid >> 8;               // 0..15, z = kk*8 + rr
        const int rr = z & 7, kk = z >> 3;
        const int e = (3 * rr + 7 * kk) & 7;
        const int m0 = ((rid >> 3) & 31) * BM;
        const int n0 = (rid & 7) * BN;
        const __half* A = g_xh + rr * C_DIM;  // token t = rr + 8*j, stride 8*C_DIM
        const __half* B = g_w1h + (size_t)e * C_DIM * HR;
        __half* outp = g_Hr + (size_t)z * 4096 * HR;
        const float* bias = b1 + e * HR;
        const int wm = warp & 3, wn = warp >> 2;

#pragma unroll
        for (int c = 0; c < NSTG - 1; c++) {
            fill_stage(A, 8 * C_DIM, B, HR, m0, n0, c,
                       Asm + c * A_ST, Bsm + c * B_ST, tid);
            asm volatile("cp.async.commit_group;");
        }

        float acc[2][8][4];
#pragma unroll
        for (int i = 0; i < 2; i++)
#pragma unroll
            for (int j = 0; j < 8; j++)
#pragma unroll
                for (int ee = 0; ee < 4; ee++) acc[i][j][ee] = 0.f;

        int s = 0, fs = NSTG - 1;
        for (int kt = 0; kt < KT; ++kt) {
            asm volatile("cp.async.wait_group %0;" :: "n"(NSTG - 2));
            __syncthreads();

            compute_stage(Asm + s * A_ST, Bsm + s * B_ST, acc, wm, wn, lane);

            if (kt + NSTG - 1 < KT)
                fill_stage(A, 8 * C_DIM, B, HR, m0, n0, kt + NSTG - 1,
                           Asm + fs * A_ST, Bsm + fs * B_ST, tid);
            asm volatile("cp.async.commit_group;");

            if (++s == NSTG) s = 0;
            if (++fs == NSTG) fs = 0;
        }

#pragma unroll
        for (int mi = 0; mi < 2; mi++)
#pragma unroll
            for (int ni = 0; ni < 8; ni++)
#pragma unroll
                for (int pp = 0; pp < 2; pp++) {
                    int row = m0 + wm * 32 + mi * 16 + (lane >> 2) + pp * 8;
                    int col = n0 + wn * 64 + ni * 8 + (lane & 3) * 2;
                    float v0 = acc[mi][ni][2 * pp + 0] + bias[col];
                    float v1 = acc[mi][ni][2 * pp + 1] + bias[col + 1];
                    v0 = 0.5f * v0 * (1.f + erff(v0 * 0.70710678118654752f));
                    v1 = 0.5f * v1 * (1.f + erff(v1 * 0.70710678118654752f));
                    *(__half2*)(outp + (size_t)row * HR + col) = __floats2half2_rn(v0, v1);
                }
    }
}

// ---------------- mega down kernel: out = 0.5*shared_down + 0.25*(y0+y1) ------
// Three K-segments accumulated into the same registers (BK=64):
//   kt in [0,32):  H2[t] @ (0.5*sw2)       (A rows strided 8*HS, residue rr)
//   kt in [32,48): Hr[rr]   @ (0.25*w2[e0])
//   kt in [48,64): Hr[8+rr] @ (0.25*w2[e1])
#define KT_MEGA 64
__device__ __forceinline__ void mega_map(int kt, int rr, int e0, int e1,
                                         const __half*& Ap, int& sA, const __half*& Bp) {
    if (kt < 32) {
        Ap = g_H2 + (size_t)rr * HS + (size_t)kt * BK;
        sA = 8 * HS;
        Bp = g_sw2h + (size_t)kt * BK * C_DIM;
    } else if (kt < 48) {
        Ap = g_Hr + (size_t)rr * 4096 * HR + (size_t)(kt - 32) * BK;
        sA = HR;
        Bp = g_w2h + (size_t)e0 * HR * C_DIM + (size_t)(kt - 32) * BK * C_DIM;
    } else {
        Ap = g_Hr + (size_t)(8 + rr) * 4096 * HR + (size_t)(kt - 48) * BK;
        sA = HR;
        Bp = g_w2h + (size_t)e1 * HR * C_DIM + (size_t)(kt - 48) * BK * C_DIM;
    }
}
__device__ __forceinline__ void fill_stage_mega(
    int kt, int rr, int e0, int e1, int m0, int n0,
    __half* Asb, __half* Bsb, int tid)
{
    const __half* Ap; const __half* Bp; int sA;
    mega_map(kt, rr, e0, e1, Ap, sA, Bp);
#pragma unroll
    for (int i = 0; i < 4; i++) {
        int c = tid + i * 256;
        int ar = c >> 3, ac = c & 7;
        cp16(Asb + ar * ASTR + ac * 8,
             Ap + (size_t)(m0 + ar) * sA + ac * 8);
    }
#pragma unroll
    for (int i = 0; i < 4; i++) {
        int c = tid + i * 256;
        int br = c >> 4, bc = c & 15;
        cp16(Bsb + br * BSTR + bc * 8,
             Bp + (size_t)br * C_DIM + n0 + bc * 8);
    }
}
__global__ __launch_bounds__(256, 2) void k_down_mega(
    const float* __restrict__ sb2, const float* __restrict__ b2,
    float* __restrict__ dout)
{
    extern __shared__ __align__(16) __half smem[];
    __half* Asm = smem;
    __half* Bsm = smem + NSTG * A_ST;

    const int rr = blockIdx.z;
    const int e0 = (3 * rr) & 7;
    const int e1 = (3 * rr + 7) & 7;
    const int tid = threadIdx.x;
    const int m0 = blockIdx.y * BM;        // logical row j within residue class
    const int n0 = blockIdx.x * BN;

#pragma unroll
    for (int c = 0; c < NSTG - 1; c++) {
        fill_stage_mega(c, rr, e0, e1, m0, n0,
                        Asm + c * A_ST, Bsm + c * B_ST, tid);
        asm volatile("cp.async.commit_group;");
    }

    float acc[2][8][4];
#pragma unroll
    for (int i = 0; i < 2; i++)
#pragma unroll
        for (int j = 0; j < 8; j++)
#pragma unroll
            for (int e = 0; e < 4; e++) acc[i][j][e] = 0.f;

    const int warp = tid >> 5, lane = tid & 31;
    const int wm = warp & 3, wn = warp >> 2;

    int s = 0, fs = NSTG - 1;
    for (int kt = 0; kt < KT_MEGA; ++kt) {
        asm volatile("cp.async.wait_group %0;" :: "n"(NSTG - 2));
        __syncthreads();

        compute_stage(Asm + s * A_ST, Bsm + s * B_ST, acc, wm, wn, lane);

        if (kt + NSTG - 1 < KT_MEGA)
            fill_stage_mega(kt + NSTG - 1, rr, e0, e1, m0, n0,
                            Asm + fs * A_ST, Bsm + fs * B_ST, tid);
        asm volatile("cp.async.commit_group;");

        if (++s == NSTG) s = 0;
        if (++fs == NSTG) fs = 0;
    }

    // epilogue: single fp32 write, combined bias
#pragma unroll
    for (int mi = 0; mi < 2; mi++)
#pragma unroll
        for (int ni = 0; ni < 8; ni++)
#pragma unroll
            for (int pp = 0; pp < 2; pp++) {
                int rowl = m0 + wm * 32 + mi * 16 + (lane >> 2) + pp * 8;
                int col  = n0 + wn * 64 + ni * 8 + (lane & 3) * 2;
                float bb0 = 0.5f * sb2[col]
                          + 0.25f * (b2[e0 * C_DIM + col] + b2[e1 * C_DIM + col]);
                float bb1 = 0.5f * sb2[col + 1]
                          + 0.25f * (b2[e0 * C_DIM + col + 1] + b2[e1 * C_DIM + col + 1]);
                float2 f;
                f.x = acc[mi][ni][2 * pp + 0] + bb0;
                f.y = acc[mi][ni][2 * pp + 1] + bb1;
                size_t t = (size_t)rr + 8 * (size_t)rowl;    // actual token
                *(float2*)(dout + t * C_DIM + col) = f;
            }
}

// ---------------- launch ----------------
extern "C" void kernel_launch(void* const* d_in, const int* in_sizes, int n_in,
                              void* d_out, int out_size) {
    const float* x   = (const float*)d_in[0];
    // d_in[1] = t_emb : unused by reference
    const float* sw1 = (const float*)d_in[2];
    const float* sb1 = (const float*)d_in[3];
    const float* sw3 = (const float*)d_in[4];
    const float* sb3 = (const float*)d_in[5];
    const float* sw2 = (const float*)d_in[6];
    const float* sb2 = (const float*)d_in[7];
    const float* w1  = (const float*)d_in[8];
    const float* b1  = (const float*)d_in[9];
    const float* w2  = (const float*)d_in[10];
    const float* b2  = (const float*)d_in[11];
    float* out = (float*)d_out;

    cudaFuncSetAttribute(k_up_all,    cudaFuncAttributeMaxDynamicSharedMemorySize, SMEM_BYTES);
    cudaFuncSetAttribute(k_down_mega, cudaFuncAttributeMaxDynamicSharedMemorySize, SMEM_BYTES);

    // fp32 -> fp16 conversions; down-proj weights pre-scaled (0.5 shared, 0.25 routed)
    {
        int n4x = (N_TOK * C_DIM) / 4;
        k_convert<<<(n4x + 255) / 256, 256>>>(x, 0, n4x, 1.0f);
        int n4w = (C_DIM * HS) / 4;
        k_convert13<<<(2 * n4w + 255) / 256, 256>>>(sw1, sw3, n4w);
        k_convert<<<(n4w + 255) / 256, 256>>>(sw2, 3, n4w, 0.5f);
        int n4e = (NE * C_DIM * HR) / 4;
        k_convert<<<(n4e + 255) / 256, 256>>>(w1, 4, n4e, 1.0f);
        k_convert<<<(n4e + 255) / 256, 256>>>(w2, 5, n4e, 0.25f);
    }

    // merged up path: shared SwiGLU (8192 CTAs) + routed gelu (4096 CTAs)
    k_up_all<<<12288, 256, SMEM_BYTES>>>(sb1, sb3, b1);

    // fused down path: single pass, single out write
    k_down_mega<<<dim3(C_DIM / BN, 4096 / BM, 8), 256, SMEM_BYTES>>>(sb2, b2, out);
}

// round 11
// speedup vs baseline: 1.9026x; 1.0003x over previous
#include <cuda_runtime.h>
#include <cuda_fp16.h>
#include <stdint.h>
#include <math.h>

// ---------------- problem constants ----------------
#define N_TOK 32768      // B*T = 4*8192
#define C_DIM 1024
#define HS    2048
#define HR    1024
#define NE    8

// Token permutation: physical row = (t & 7) * 4096 + (t >> 3)  (residue-major).
// g_xh and g_H2 are stored in this permuted order; all GEMM A-streams are
// then fully contiguous. Only the final dout store un-permutes.

// ---------------- GEMM tile config ----------------
#define BM 128
#define BN 128
#define BK 64
#define NSTG 3
#define ASTR (BK + 8)    // 72 halfs/row (144B, conflict-free ldmatrix)
#define BSTR (BN + 8)    // 136 halfs/row (272B, conflict-free ldmatrix.trans)
#define A_ST (BM * ASTR)             // 9216 halfs per A stage
#define B_ST (BK * BSTR)             // 8704 halfs per B stage
#define SMEM_BYTES (NSTG * (A_ST + B_ST) * 2)   // 107520 B -> 2 CTAs/SM

// ---------------- static scratch (no allocations allowed) ----------------
__device__ __half g_xh[N_TOK * C_DIM];          // x fp16, residue-major permuted
__device__ __half g_sw1h[C_DIM * HS];
__device__ __half g_sw3h[C_DIM * HS];
__device__ __half g_sw2h[HS * C_DIM];           // pre-scaled by 0.5
__device__ __half g_w1h[NE * C_DIM * HR];
__device__ __half g_w2h[NE * HR * C_DIM];       // pre-scaled by 0.25
__device__ __half g_H2[N_TOK * HS];             // swiglu hidden, permuted rows
__device__ __half g_Hr[2 * N_TOK * HR];         // routed hidden [k*8+r][4096][HR]

// ---------------- small PTX helpers ----------------
__device__ __forceinline__ void cp16(void* s, const void* g) {
    unsigned sa = (unsigned)__cvta_generic_to_shared(s);
    asm volatile("cp.async.cg.shared.global [%0], [%1], 16;" :: "r"(sa), "l"(g));
}
__device__ __forceinline__ void ldsm4(uint32_t* r, const __half* p) {
    unsigned a = (unsigned)__cvta_generic_to_shared(p);
    asm volatile("ldmatrix.sync.aligned.m8n8.x4.shared.b16 {%0,%1,%2,%3}, [%4];"
                 : "=r"(r[0]), "=r"(r[1]), "=r"(r[2]), "=r"(r[3]) : "r"(a));
}
__device__ __forceinline__ void ldsm4t(uint32_t* r, const __half* p) {
    unsigned a = (unsigned)__cvta_generic_to_shared(p);
    asm volatile("ldmatrix.sync.aligned.m8n8.x4.trans.shared.b16 {%0,%1,%2,%3}, [%4];"
                 : "=r"(r[0]), "=r"(r[1]), "=r"(r[2]), "=r"(r[3]) : "r"(a));
}
__device__ __forceinline__ void mma16816(float* d, const uint32_t* a, const uint32_t* b) {
    asm volatile(
        "mma.sync.aligned.m16n8k16.row.col.f32.f16.f16.f32 "
        "{%0,%1,%2,%3},{%4,%5,%6,%7},{%8,%9},{%0,%1,%2,%3};"
        : "+f"(d[0]), "+f"(d[1]), "+f"(d[2]), "+f"(d[3])
        : "r"(a[0]), "r"(a[1]), "r"(a[2]), "r"(a[3]), "r"(b[0]), "r"(b[1]));
}

// ---------------- conversion kernels ----------------
// x: fp32 -> fp16 with residue-major row permutation (writes stay row-coalesced)
__global__ void k_convx(const float* __restrict__ src, int n4) {
    int i = blockIdx.x * blockDim.x + threadIdx.x;
    if (i >= n4) return;
    int t = i >> 8;                 // token (C_DIM/4 = 256 float4 per row)
    int c = i & 255;
    int pr = ((t & 7) << 12) | (t >> 3);   // permuted row
    float4 v = ((const float4*)src)[i];
    __half2* d = (__half2*)g_xh + (size_t)pr * (C_DIM / 2) + c * 2;
    d[0] = __floats2half2_rn(v.x, v.y);
    d[1] = __floats2half2_rn(v.z, v.w);
}
__device__ __forceinline__ __half* conv_dst(int tag) {
    switch (tag) {
        case 3: return g_sw2h;
        case 4: return g_w1h;
        default: return g_w2h;
    }
}
__global__ void k_convert(const float* __restrict__ src, int tag, int n4, float scale) {
    int i = blockIdx.x * blockDim.x + threadIdx.x;
    if (i >= n4) return;
    float4 v = ((const float4*)src)[i];
    __half2* d = (__half2*)conv_dst(tag);
    d[2 * i]     = __floats2half2_rn(v.x * scale, v.y * scale);
    d[2 * i + 1] = __floats2half2_rn(v.z * scale, v.w * scale);
}
__global__ void k_convert13(const float* __restrict__ s1, const float* __restrict__ s3, int n4) {
    int i = blockIdx.x * blockDim.x + threadIdx.x;
    const float* src; __half2* d;
    if (i < n4)           { src = s1; d = (__half2*)g_sw1h; }
    else if (i < 2 * n4)  { src = s3; d = (__half2*)g_sw3h; i -= n4; }
    else return;
    float4 v = ((const float4*)src)[i];
    d[2 * i]     = __floats2half2_rn(v.x, v.y);
    d[2 * i + 1] = __floats2half2_rn(v.z, v.w);
}

// ---------------- generic stage fill (BK=64, cp.async) ----------------
__device__ __forceinline__ void fill_stage(
    const __half* __restrict__ A, int strideA,
    const __half* __restrict__ B, int ldb,
    int m0, int n0, int kt, __half* Asb, __half* Bsb, int tid)
{
#pragma unroll
    for (int i = 0; i < 4; i++) {              // A: 128x64 halfs = 1024 x 16B chunks
        int c = tid + i * 256;
        int ar = c >> 3, ac = c & 7;
        cp16(Asb + ar * ASTR + ac * 8,
             A + (size_t)(m0 + ar) * strideA + kt * BK + ac * 8);
    }
#pragma unroll
    for (int i = 0; i < 4; i++) {              // B: 64x128 halfs = 1024 x 16B chunks
        int c = tid + i * 256;
        int br = c >> 4, bc = c & 15;
        cp16(Bsb + br * BSTR + bc * 8,
             B + (size_t)(kt * BK + br) * ldb + n0 + bc * 8);
    }
}

// ---------------- warp-tile compute on one resident stage (128x128, BK=64) ----------
__device__ __forceinline__ void compute_stage(
    const __half* As, const __half* Bs, float acc[2][8][4],
    int wm, int wn, int lane)
{
#pragma unroll
    for (int ks = 0; ks < 4; ks++) {           // four k16 steps per BK=64
        uint32_t a[2][4];
#pragma unroll
        for (int mi = 0; mi < 2; mi++) {
            const __half* p = &As[(wm * 32 + mi * 16 + (lane & 15)) * ASTR
                                  + ks * 16 + (lane >> 4) * 8];
            ldsm4(a[mi], p);
        }
#pragma unroll
        for (int p4 = 0; p4 < 4; p4++) {       // 16 cols per ldmatrix.x4.trans
            uint32_t b[4];
            const __half* p = &Bs[(ks * 16 + (lane & 7) + ((lane >> 3) & 1) * 8) * BSTR
                                  + wn * 64 + p4 * 16 + (lane >> 4) * 8];
            ldsm4t(b, p);
            mma16816(acc[0][2 * p4 + 0], a[0], &b[0]);
            mma16816(acc[0][2 * p4 + 1], a[0], &b[2]);
            mma16816(acc[1][2 * p4 + 0], a[1], &b[0]);
            mma16816(acc[1][2 * p4 + 1], a[1], &b[2]);
        }
    }
}

// ---------------- up-fused stage fill: A=x(perm), B=[sw1 64cols | sw3 64cols] -----
__device__ __forceinline__ void fill_stage_up(
    int kt, int m0, int n0, __half* Asb, __half* Bsb, int tid)
{
#pragma unroll
    for (int i = 0; i < 4; i++) {              // A: 128x64 halfs
        int c = tid + i * 256;
        int ar = c >> 3, ac = c & 7;
        cp16(Asb + ar * ASTR + ac * 8,
             g_xh + (size_t)(m0 + ar) * C_DIM + kt * BK + ac * 8);
    }
#pragma unroll
    for (int i = 0; i < 4; i++) {              // B: 64 rows x (64|64) halfs
        int c = tid + i * 256;
        int br = c >> 4, bc = c & 15;
        if (bc < 8)
            cp16(Bsb + br * BSTR + bc * 8,
                 g_sw1h + (size_t)(kt * BK + br) * HS + n0 + bc * 8);
        else
            cp16(Bsb + br * BSTR + 64 + (bc - 8) * 8,
                 g_sw3h + (size_t)(kt * BK + br) * HS + n0 + (bc - 8) * 8);
    }
}

// ================= merged UP kernel ==========================================
// 1D grid, 12288 CTAs:
//   bid < 8192 : shared-up tile (128 permuted rows x 64 H2-cols, both branches)
//   bid >= 8192: routed-up tile (128x128, gelu)
__global__ __launch_bounds__(256, 2) void k_up_all(
    const float* __restrict__ sb1, const float* __restrict__ sb3,
    const float* __restrict__ b1)
{
    extern __shared__ __align__(16) __half smem[];
    __half* Asm = smem;
    __half* Bsm = smem + NSTG * A_ST;

    const int tid = threadIdx.x;
    const int bid = blockIdx.x;
    const int warp = tid >> 5, lane = tid & 31;
    const int KT = C_DIM / BK;                 // 16

    if (bid < 8192) {
        // ---------- shared up: H2 = silu(x@sw1+b1)*(x@sw3+b3) ----------
        const int m0 = (bid >> 5) * BM;
        const int n0 = (bid & 31) * 64;
        const int wm = warp & 3, wn = (warp >> 2) & 1;

#pragma unroll
        for (int c = 0; c < NSTG - 1; c++) {
            fill_stage_up(c, m0, n0, Asm + c * A_ST, Bsm + c * B_ST, tid);
            asm volatile("cp.async.commit_group;");
        }

        float acc1[2][4][4], acc3[2][4][4];
#pragma unroll
        for (int i = 0; i < 2; i++)
#pragma unroll
            for (int j = 0; j < 4; j++)
#pragma unroll
                for (int e = 0; e < 4; e++) { acc1[i][j][e] = 0.f; acc3[i][j][e] = 0.f; }

        int s = 0, fs = NSTG - 1;
        for (int kt = 0; kt < KT; ++kt) {
            asm volatile("cp.async.wait_group %0;" :: "n"(NSTG - 2));
            __syncthreads();

            const __half* As = Asm + s * A_ST;
            const __half* Bs = Bsm + s * B_ST;
#pragma unroll
            for (int ks = 0; ks < 4; ks++) {
                uint32_t a[2][4];
#pragma unroll
                for (int mi = 0; mi < 2; mi++) {
                    const __half* p = &As[(wm * 32 + mi * 16 + (lane & 15)) * ASTR
                                          + ks * 16 + (lane >> 4) * 8];
                    ldsm4(a[mi], p);
                }
                const int brow = (ks * 16 + (lane & 7) + ((lane >> 3) & 1) * 8) * BSTR
                                 + (lane >> 4) * 8;
#pragma unroll
                for (int p4 = 0; p4 < 2; p4++) {   // branch 1 (sw1)
                    uint32_t b[4];
                    ldsm4t(b, &Bs[brow + wn * 32 + p4 * 16]);
                    mma16816(acc1[0][2 * p4 + 0], a[0], &b[0]);
                    mma16816(acc1[0][2 * p4 + 1], a[0], &b[2]);
                    mma16816(acc1[1][2 * p4 + 0], a[1], &b[0]);
                    mma16816(acc1[1][2 * p4 + 1], a[1], &b[2]);
                }
#pragma unroll
                for (int p4 = 0; p4 < 2; p4++) {   // branch 3 (sw3): +64 col offset
                    uint32_t b[4];
                    ldsm4t(b, &Bs[brow + 64 + wn * 32 + p4 * 16]);
                    mma16816(acc3[0][2 * p4 + 0], a[0], &b[0]);
                    mma16816(acc3[0][2 * p4 + 1], a[0], &b[2]);
                    mma16816(acc3[1][2 * p4 + 0], a[1], &b[0]);
                    mma16816(acc3[1][2 * p4 + 1], a[1], &b[2]);
                }
            }

            if (kt + NSTG - 1 < KT)
                fill_stage_up(kt + NSTG - 1, m0, n0,
                              Asm + fs * A_ST, Bsm + fs * B_ST, tid);
            asm volatile("cp.async.commit_group;");

            if (++s == NSTG) s = 0;
            if (++fs == NSTG) fs = 0;
        }

#pragma unroll
        for (int mi = 0; mi < 2; mi++)
#pragma unroll
            for (int ni = 0; ni < 4; ni++)
#pragma unroll
                for (int pp = 0; pp < 2; pp++) {
                    int row = m0 + wm * 32 + mi * 16 + (lane >> 2) + pp * 8;
                    int col = n0 + wn * 32 + ni * 8 + (lane & 3) * 2;
                    float u0 = acc1[mi][ni][2 * pp + 0] + sb1[col];
                    float u1 = acc1[mi][ni][2 * pp + 1] + sb1[col + 1];
                    float w0 = acc3[mi][ni][2 * pp + 0] + sb3[col];
                    float w1 = acc3[mi][ni][2 * pp + 1] + sb3[col + 1];
                    float v0 = u0 / (1.f + __expf(-u0)) * w0;
                    float v1 = u1 / (1.f + __expf(-u1)) * w1;
                    *(__half2*)(g_H2 + (size_t)row * HS + col) = __floats2half2_rn(v0, v1);
                }
    } else {
        // ---------- routed up: Hr[z] = gelu(x_perm[rr block] @ w1[e] + b1[e]) ------
        const int rid = bid - 8192;
        const int z = rid >> 8;               // 0..15, z = kk*8 + rr
        const int rr = z & 7, kk = z >> 3;
        const int e = (3 * rr + 7 * kk) & 7;
        const int m0 = ((rid >> 3) & 31) * BM;
        const int n0 = (rid & 7) * BN;
        // permuted layout: residue block rr = rows [rr*4096, rr*4096+4096), contiguous
        const __half* A = g_xh + (size_t)rr * 4096 * C_DIM;
        const __half* B = g_w1h + (size_t)e * C_DIM * HR;
        __half* outp = g_Hr + (size_t)z * 4096 * HR;
        const float* bias = b1 + e * HR;
        const int wm = warp & 3, wn = warp >> 2;

#pragma unroll
        for (int c = 0; c < NSTG - 1; c++) {
            fill_stage(A, C_DIM, B, HR, m0, n0, c,
                       Asm + c * A_ST, Bsm + c * B_ST, tid);
            asm volatile("cp.async.commit_group;");
        }

        float acc[2][8][4];
#pragma unroll
        for (int i = 0; i < 2; i++)
#pragma unroll
            for (int j = 0; j < 8; j++)
#pragma unroll
                for (int ee = 0; ee < 4; ee++) acc[i][j][ee] = 0.f;

        int s = 0, fs = NSTG - 1;
        for (int kt = 0; kt < KT; ++kt) {
            asm volatile("cp.async.wait_group %0;" :: "n"(NSTG - 2));
            __syncthreads();

            compute_stage(Asm + s * A_ST, Bsm + s * B_ST, acc, wm, wn, lane);

            if (kt + NSTG - 1 < KT)
                fill_stage(A, C_DIM, B, HR, m0, n0, kt + NSTG - 1,
                           Asm + fs * A_ST, Bsm + fs * B_ST, tid);
            asm volatile("cp.async.commit_group;");

            if (++s == NSTG) s = 0;
            if (++fs == NSTG) fs = 0;
        }

#pragma unroll
        for (int mi = 0; mi < 2; mi++)
#pragma unroll
            for (int ni = 0; ni < 8; ni++)
#pragma unroll
                for (int pp = 0; pp < 2; pp++) {
                    int row = m0 + wm * 32 + mi * 16 + (lane >> 2) + pp * 8;
                    int col = n0 + wn * 64 + ni * 8 + (lane & 3) * 2;
                    float v0 = acc[mi][ni][2 * pp + 0] + bias[col];
                    float v1 = acc[mi][ni][2 * pp + 1] + bias[col + 1];
                    v0 = 0.5f * v0 * (1.f + erff(v0 * 0.70710678118654752f));
                    v1 = 0.5f * v1 * (1.f + erff(v1 * 0.70710678118654752f));
                    *(__half2*)(outp + (size_t)row * HR + col) = __floats2half2_rn(v0, v1);
                }
    }
}

// ---------------- mega down kernel: out = 0.5*shared_down + 0.25*(y0+y1) ------
// Three K-segments accumulated into the same registers (BK=64), all contiguous A:
//   kt in [0,32):  H2_perm[rr block] @ (0.5*sw2)
//   kt in [32,48): Hr[rr]   @ (0.25*w2[e0])
//   kt in [48,64): Hr[8+rr] @ (0.25*w2[e1])
#define KT_MEGA 64
__device__ __forceinline__ void mega_map(int kt, int rr, int e0, int e1,
                                         const __half*& Ap, int& sA, const __half*& Bp) {
    if (kt < 32) {
        Ap = g_H2 + (size_t)rr * 4096 * HS + (size_t)kt * BK;
        sA = HS;
        Bp = g_sw2h + (size_t)kt * BK * C_DIM;
    } else if (kt < 48) {
        Ap = g_Hr + (size_t)rr * 4096 * HR + (size_t)(kt - 32) * BK;
        sA = HR;
        Bp = g_w2h + (size_t)e0 * HR * C_DIM + (size_t)(kt - 32) * BK * C_DIM;
    } else {
        Ap = g_Hr + (size_t)(8 + rr) * 4096 * HR + (size_t)(kt - 48) * BK;
        sA = HR;
        Bp = g_w2h + (size_t)e1 * HR * C_DIM + (size_t)(kt - 48) * BK * C_DIM;
    }
}
__device__ __forceinline__ void fill_stage_mega(
    int kt, int rr, int e0, int e1, int m0, int n0,
    __half* Asb, __half* Bsb, int tid)
{
    const __half* Ap; const __half* Bp; int sA;
    mega_map(kt, rr, e0, e1, Ap, sA, Bp);
#pragma unroll
    for (int i = 0; i < 4; i++) {
        int c = tid + i * 256;
        int ar = c >> 3, ac = c & 7;
        cp16(Asb + ar * ASTR + ac * 8,
             Ap + (size_t)(m0 + ar) * sA + ac * 8);
    }
#pragma unroll
    for (int i = 0; i < 4; i++) {
        int c = tid + i * 256;
        int br = c >> 4, bc = c & 15;
        cp16(Bsb + br * BSTR + bc * 8,
             Bp + (size_t)br * C_DIM + n0 + bc * 8);
    }
}
__global__ __launch_bounds__(256, 2) void k_down_mega(
    const float* __restrict__ sb2, const float* __restrict__ b2,
    float* __restrict__ dout)
{
    extern __shared__ __align__(16) __half smem[];
    __half* Asm = smem;
    __half* Bsm = smem + NSTG * A_ST;

    const int rr = blockIdx.z;
    const int e0 = (3 * rr) & 7;
    const int e1 = (3 * rr + 7) & 7;
    const int tid = threadIdx.x;
    const int m0 = blockIdx.y * BM;        // logical row j within residue class
    const int n0 = blockIdx.x * BN;

#pragma unroll
    for (int c = 0; c < NSTG - 1; c++) {
        fill_stage_mega(c, rr, e0, e1, m0, n0,
                        Asm + c * A_ST, Bsm + c * B_ST, tid);
        asm volatile("cp.async.commit_group;");
    }

    float acc[2][8][4];
#pragma unroll
    for (int i = 0; i < 2; i++)
#pragma unroll
        for (int j = 0; j < 8; j++)
#pragma unroll
            for (int e = 0; e < 4; e++) acc[i][j][e] = 0.f;

    const int warp = tid >> 5, lane = tid & 31;
    const int wm = warp & 3, wn = warp >> 2;

    int s = 0, fs = NSTG - 1;
    for (int kt = 0; kt < KT_MEGA; ++kt) {
        asm volatile("cp.async.wait_group %0;" :: "n"(NSTG - 2));
        __syncthreads();

        compute_stage(Asm + s * A_ST, Bsm + s * B_ST, acc, wm, wn, lane);

        if (kt + NSTG - 1 < KT_MEGA)
            fill_stage_mega(kt + NSTG - 1, rr, e0, e1, m0, n0,
                            Asm + fs * A_ST, Bsm + fs * B_ST, tid);
        asm volatile("cp.async.commit_group;");

        if (++s == NSTG) s = 0;
        if (++fs == NSTG) fs = 0;
    }

    // epilogue: single fp32 write, combined bias, un-permute rows
#pragma unroll
    for (int mi = 0; mi < 2; mi++)
#pragma unroll
        for (int ni = 0; ni < 8; ni++)
#pragma unroll
            for (int pp = 0; pp < 2; pp++) {
                int rowl = m0 + wm * 32 + mi * 16 + (lane >> 2) + pp * 8;
                int col  = n0 + wn * 64 + ni * 8 + (lane & 3) * 2;
                float bb0 = 0.5f * sb2[col]
                          + 0.25f * (b2[e0 * C_DIM + col] + b2[e1 * C_DIM + col]);
                float bb1 = 0.5f * sb2[col + 1]
                          + 0.25f * (b2[e0 * C_DIM + col + 1] + b2[e1 * C_DIM + col + 1]);
                float2 f;
                f.x = acc[mi][ni][2 * pp + 0] + bb0;
                f.y = acc[mi][ni][2 * pp + 1] + bb1;
                size_t t = (size_t)rr + 8 * (size_t)rowl;    // actual token
                *(float2*)(dout + t * C_DIM + col) = f;
            }
}

// ---------------- launch ----------------
extern "C" void kernel_launch(void* const* d_in, const int* in_sizes, int n_in,
                              void* d_out, int out_size) {
    const float* x   = (const float*)d_in[0];
    // d_in[1] = t_emb : unused by reference
    const float* sw1 = (const float*)d_in[2];
    const float* sb1 = (const float*)d_in[3];
    const float* sw3 = (const float*)d_in[4];
    const float* sb3 = (const float*)d_in[5];
    const float* sw2 = (const float*)d_in[6];
    const float* sb2 = (const float*)d_in[7];
    const float* w1  = (const float*)d_in[8];
    const float* b1  = (const float*)d_in[9];
    const float* w2  = (const float*)d_in[10];
    const float* b2  = (const float*)d_in[11];
    float* out = (float*)d_out;

    cudaFuncSetAttribute(k_up_all,    cudaFuncAttributeMaxDynamicSharedMemorySize, SMEM_BYTES);
    cudaFuncSetAttribute(k_down_mega, cudaFuncAttributeMaxDynamicSharedMemorySize, SMEM_BYTES);

    // fp32 -> fp16 conversions; x permuted residue-major;
    // down-proj weights pre-scaled (0.5 shared, 0.25 routed)
    {
        int n4x = (N_TOK * C_DIM) / 4;
        k_convx<<<(n4x + 255) / 256, 256>>>(x, n4x);
        int n4w = (C_DIM * HS) / 4;
        k_convert13<<<(2 * n4w + 255) / 256, 256>>>(sw1, sw3, n4w);
        k_convert<<<(n4w + 255) / 256, 256>>>(sw2, 3, n4w, 0.5f);
        int n4e = (NE * C_DIM * HR) / 4;
        k_convert<<<(n4e + 255) / 256, 256>>>(w1, 4, n4e, 1.0f);
        k_convert<<<(n4e + 255) / 256, 256>>>(w2, 5, n4e, 0.25f);
    }

    // merged up path: shared SwiGLU (8192 CTAs) + routed gelu (4096 CTAs)
    k_up_all<<<12288, 256, SMEM_BYTES>>>(sb1, sb3, b1);

    // fused down path: single pass, single out write
    k_down_mega<<<dim3(C_DIM / BN, 4096 / BM, 8), 256, SMEM_BYTES>>>(sb2, b2, out);
}